// round 2
// baseline (speedup 1.0000x reference)
#include <cuda_runtime.h>
#include <cuda_bf16.h>
#include <math.h>

#define NN 50000
#define EE 1600000
#define ET (EE + NN)     // edges + self loops
#define GG 100
#define IN_CH 16
#define H1 4
#define C1 32
#define D1 (H1*C1)       // 128
#define C2 32
#define NEG 0.2f

// ---------------- scratch (static device globals; no allocation) ----------------
__device__ int   g_deg[NN];
__device__ int   g_rowptr[NN + 1];
__device__ int   g_cursor[NN];
__device__ int   g_csrsrc[ET];
__device__ __align__(16) float g_h1[NN * D1];
__device__ __align__(16) float g_as1[NN * H1];
__device__ __align__(16) float g_ad1[NN * H1];
__device__ __align__(16) float g_out1[NN * D1];
__device__ __align__(16) float g_h2[NN * C2];
__device__ float g_as2[NN];
__device__ float g_ad2[NN];
__device__ float g_pool[GG * C2];
__device__ float g_cnt[GG];

// ---------------- init ----------------
__global__ void k_init() {
    int i = blockIdx.x * blockDim.x + threadIdx.x;
    if (i < NN) g_deg[i] = 1;           // self loop
    if (i < GG * C2) g_pool[i] = 0.f;
    if (i < GG) g_cnt[i] = 0.f;
}

// ---------------- degree count (edge_index is int32!) ----------------
__global__ void k_degree(const int* __restrict__ ei) {
    int e = blockIdx.x * blockDim.x + threadIdx.x;
    if (e >= EE) return;
    int dst = ei[EE + e];
    atomicAdd(&g_deg[dst], 1);
}

// ---------------- single-block exclusive scan (shuffle-based) ----------------
__global__ void k_scan() {
    __shared__ int warp_sums[32];
    __shared__ int carry_s;
    int t = threadIdx.x;
    int lane = t & 31, warp = t >> 5;
    if (t == 0) carry_s = 0;
    __syncthreads();
    for (int base = 0; base < NN; base += 1024) {
        int idx = base + t;
        int v = (idx < NN) ? g_deg[idx] : 0;
        // warp inclusive scan
        int incl = v;
        #pragma unroll
        for (int off = 1; off < 32; off <<= 1) {
            int n = __shfl_up_sync(0xffffffffu, incl, off);
            if (lane >= off) incl += n;
        }
        if (lane == 31) warp_sums[warp] = incl;
        __syncthreads();
        if (warp == 0) {
            int ws = warp_sums[lane];
            int wincl = ws;
            #pragma unroll
            for (int off = 1; off < 32; off <<= 1) {
                int n = __shfl_up_sync(0xffffffffu, wincl, off);
                if (lane >= off) wincl += n;
            }
            warp_sums[lane] = wincl - ws;   // exclusive warp offset
        }
        __syncthreads();
        int carry = carry_s;
        int total_pos = carry + warp_sums[warp] + incl;   // inclusive with carry
        if (idx < NN) g_rowptr[idx] = total_pos - v;      // exclusive
        __syncthreads();
        if (t == 1023) carry_s = total_pos;
        __syncthreads();
    }
    if (t == 0) g_rowptr[NN] = carry_s;
}

__global__ void k_cursor() {
    int i = blockIdx.x * blockDim.x + threadIdx.x;
    if (i < NN) g_cursor[i] = g_rowptr[i];
}

// ---------------- scatter edges into CSR (by dst), incl. self loops ----------------
__global__ void k_scatter(const int* __restrict__ ei) {
    int idx = blockIdx.x * blockDim.x + threadIdx.x;
    if (idx >= ET) return;
    int src, dst;
    if (idx < EE) { src = ei[idx]; dst = ei[EE + idx]; }
    else          { src = idx - EE; dst = src; }
    int slot = atomicAdd(&g_cursor[dst], 1);
    g_csrsrc[slot] = src;
}

// ---------------- GEMM1 + attention logits ----------------
// block = 256 threads = 8 warps = 2 node-groups x 4 heads.
__global__ void k_gemm1(const float* __restrict__ x,
                        const float* __restrict__ W1,
                        const float* __restrict__ as_w,
                        const float* __restrict__ ad_w) {
    __shared__ float sW[IN_CH * D1];   // 8KB
    __shared__ float sAs[H1 * C1];
    __shared__ float sAd[H1 * C1];
    int t = threadIdx.x;
    for (int i = t; i < IN_CH * D1; i += 256) sW[i] = W1[i];
    if (t < H1 * C1) { sAs[t] = as_w[t]; sAd[t] = ad_w[t]; }
    __syncthreads();

    int warp = t >> 5, lane = t & 31;
    int h = warp & 3;
    int n = blockIdx.x * 64 + (warp >> 2) * 32 + lane;
    if (n >= NN) return;

    float xv[16];
    const float4* xp = (const float4*)(x + (size_t)n * IN_CH);
    #pragma unroll
    for (int i = 0; i < 4; i++) {
        float4 r = xp[i];
        xv[4*i]=r.x; xv[4*i+1]=r.y; xv[4*i+2]=r.z; xv[4*i+3]=r.w;
    }

    float acc[C1];
    #pragma unroll
    for (int c = 0; c < C1; c++) acc[c] = 0.f;
    #pragma unroll
    for (int k = 0; k < IN_CH; k++) {
        float xk = xv[k];
        const float* wrow = sW + k * D1 + h * C1;
        #pragma unroll
        for (int c = 0; c < C1; c++) acc[c] += xk * wrow[c];
    }
    float asum = 0.f, dsum = 0.f;
    #pragma unroll
    for (int c = 0; c < C1; c++) { asum += acc[c] * sAs[h*C1+c]; dsum += acc[c] * sAd[h*C1+c]; }
    g_as1[n * H1 + h] = asum;
    g_ad1[n * H1 + h] = dsum;
    float4* hp = (float4*)(g_h1 + (size_t)n * D1 + h * C1);
    #pragma unroll
    for (int i = 0; i < 8; i++) hp[i] = make_float4(acc[4*i], acc[4*i+1], acc[4*i+2], acc[4*i+3]);
}

__device__ __forceinline__ float lrelu(float e) { return e > 0.f ? e : NEG * e; }
__device__ __forceinline__ float elu(float v)   { return v > 0.f ? v : expm1f(v); }

// ---------------- fused GAT layer 1 edge kernel: warp per dst node ----------------
__global__ void k_edge1(const float* __restrict__ b1) {
    int gwarp = (blockIdx.x * blockDim.x + threadIdx.x) >> 5;
    int lane = threadIdx.x & 31;
    if (gwarp >= NN) return;
    int n = gwarp;
    int beg = g_rowptr[n], end = g_rowptr[n + 1];
    float4 ad = *(const float4*)(g_ad1 + n * 4);

    // pass 1: max
    float m0=-1e30f, m1=-1e30f, m2=-1e30f, m3=-1e30f;
    for (int i = beg + lane; i < end; i += 32) {
        int s = g_csrsrc[i];
        float4 as = *(const float4*)(g_as1 + s * 4);
        m0 = fmaxf(m0, lrelu(as.x + ad.x));
        m1 = fmaxf(m1, lrelu(as.y + ad.y));
        m2 = fmaxf(m2, lrelu(as.z + ad.z));
        m3 = fmaxf(m3, lrelu(as.w + ad.w));
    }
    #pragma unroll
    for (int off = 16; off; off >>= 1) {
        m0 = fmaxf(m0, __shfl_xor_sync(0xffffffffu, m0, off));
        m1 = fmaxf(m1, __shfl_xor_sync(0xffffffffu, m1, off));
        m2 = fmaxf(m2, __shfl_xor_sync(0xffffffffu, m2, off));
        m3 = fmaxf(m3, __shfl_xor_sync(0xffffffffu, m3, off));
    }
    // pass 2: sum of exp
    float s0=0.f, s1=0.f, s2=0.f, s3=0.f;
    for (int i = beg + lane; i < end; i += 32) {
        int s = g_csrsrc[i];
        float4 as = *(const float4*)(g_as1 + s * 4);
        s0 += __expf(lrelu(as.x + ad.x) - m0);
        s1 += __expf(lrelu(as.y + ad.y) - m1);
        s2 += __expf(lrelu(as.z + ad.z) - m2);
        s3 += __expf(lrelu(as.w + ad.w) - m3);
    }
    #pragma unroll
    for (int off = 16; off; off >>= 1) {
        s0 += __shfl_xor_sync(0xffffffffu, s0, off);
        s1 += __shfl_xor_sync(0xffffffffu, s1, off);
        s2 += __shfl_xor_sync(0xffffffffu, s2, off);
        s3 += __shfl_xor_sync(0xffffffffu, s3, off);
    }
    float i0 = 1.f / (s0 + 1e-16f), i1 = 1.f / (s1 + 1e-16f);
    float i2 = 1.f / (s2 + 1e-16f), i3 = 1.f / (s3 + 1e-16f);

    // pass 3: weighted aggregation; alpha computed per-lane-chunk, shuffled
    float acc0=0.f, acc1=0.f, acc2=0.f, acc3=0.f;
    for (int base = beg; base < end; base += 32) {
        int i = base + lane;
        int sv = 0; float a0=0.f, a1=0.f, a2=0.f, a3=0.f;
        if (i < end) {
            sv = g_csrsrc[i];
            float4 as = *(const float4*)(g_as1 + sv * 4);
            a0 = __expf(lrelu(as.x + ad.x) - m0) * i0;
            a1 = __expf(lrelu(as.y + ad.y) - m1) * i1;
            a2 = __expf(lrelu(as.z + ad.z) - m2) * i2;
            a3 = __expf(lrelu(as.w + ad.w) - m3) * i3;
        }
        int cnt = min(32, end - base);
        for (int j = 0; j < cnt; j++) {
            int s  = __shfl_sync(0xffffffffu, sv, j);
            float f0 = __shfl_sync(0xffffffffu, a0, j);
            float f1 = __shfl_sync(0xffffffffu, a1, j);
            float f2 = __shfl_sync(0xffffffffu, a2, j);
            float f3 = __shfl_sync(0xffffffffu, a3, j);
            const float* hp = g_h1 + (size_t)s * D1;
            acc0 += f0 * hp[lane];
            acc1 += f1 * hp[32 + lane];
            acc2 += f2 * hp[64 + lane];
            acc3 += f3 * hp[96 + lane];
        }
    }
    float* op = g_out1 + (size_t)n * D1;
    float v;
    v = acc0 + b1[lane];      op[lane]      = elu(v);
    v = acc1 + b1[32 + lane]; op[32 + lane] = elu(v);
    v = acc2 + b1[64 + lane]; op[64 + lane] = elu(v);
    v = acc3 + b1[96 + lane]; op[96 + lane] = elu(v);
}

// ---------------- GEMM2 + attention logits (thread per node) ----------------
__global__ void k_gemm2(const float* __restrict__ W2,
                        const float* __restrict__ as_w,
                        const float* __restrict__ ad_w) {
    __shared__ float sW[D1 * C2];   // 16KB
    __shared__ float sAs[C2], sAd[C2];
    int t = threadIdx.x;
    for (int i = t; i < D1 * C2; i += 256) sW[i] = W2[i];
    if (t < C2) { sAs[t] = as_w[t]; sAd[t] = ad_w[t]; }
    __syncthreads();
    int n = blockIdx.x * blockDim.x + t;
    if (n >= NN) return;

    float acc[C2];
    #pragma unroll
    for (int c = 0; c < C2; c++) acc[c] = 0.f;
    const float4* xp = (const float4*)(g_out1 + (size_t)n * D1);
    for (int k4 = 0; k4 < 32; k4++) {
        float4 xv = xp[k4];
        const float* w0 = sW + (k4 * 4) * C2;
        #pragma unroll
        for (int c = 0; c < C2; c++) {
            acc[c] += xv.x * w0[c] + xv.y * w0[C2 + c] + xv.z * w0[2*C2 + c] + xv.w * w0[3*C2 + c];
        }
    }
    float asum = 0.f, dsum = 0.f;
    #pragma unroll
    for (int c = 0; c < C2; c++) { asum += acc[c] * sAs[c]; dsum += acc[c] * sAd[c]; }
    g_as2[n] = asum;
    g_ad2[n] = dsum;
    float4* hp = (float4*)(g_h2 + (size_t)n * C2);
    #pragma unroll
    for (int i = 0; i < 8; i++) hp[i] = make_float4(acc[4*i], acc[4*i+1], acc[4*i+2], acc[4*i+3]);
}

// ---------------- fused GAT layer 2 edge kernel + pooling ----------------
__global__ void k_edge2(const float* __restrict__ b2,
                        const int* __restrict__ batch) {
    int gwarp = (blockIdx.x * blockDim.x + threadIdx.x) >> 5;
    int lane = threadIdx.x & 31;
    if (gwarp >= NN) return;
    int n = gwarp;
    int beg = g_rowptr[n], end = g_rowptr[n + 1];
    float ad = g_ad2[n];

    float m = -1e30f;
    for (int i = beg + lane; i < end; i += 32) {
        int s = g_csrsrc[i];
        m = fmaxf(m, lrelu(g_as2[s] + ad));
    }
    #pragma unroll
    for (int off = 16; off; off >>= 1) m = fmaxf(m, __shfl_xor_sync(0xffffffffu, m, off));

    float ssum = 0.f;
    for (int i = beg + lane; i < end; i += 32) {
        int s = g_csrsrc[i];
        ssum += __expf(lrelu(g_as2[s] + ad) - m);
    }
    #pragma unroll
    for (int off = 16; off; off >>= 1) ssum += __shfl_xor_sync(0xffffffffu, ssum, off);
    float inv = 1.f / (ssum + 1e-16f);

    float acc = 0.f;
    for (int base = beg; base < end; base += 32) {
        int i = base + lane;
        int sv = 0; float a = 0.f;
        if (i < end) {
            sv = g_csrsrc[i];
            a = __expf(lrelu(g_as2[sv] + ad) - m) * inv;
        }
        int cnt = min(32, end - base);
        for (int j = 0; j < cnt; j++) {
            int s = __shfl_sync(0xffffffffu, sv, j);
            float f = __shfl_sync(0xffffffffu, a, j);
            acc += f * g_h2[(size_t)s * C2 + lane];
        }
    }
    float v = elu(acc + b2[lane]);
    int gid = batch[n];
    atomicAdd(&g_pool[gid * C2 + lane], v);
    if (lane == 0) atomicAdd(&g_cnt[gid], 1.0f);
}

// ---------------- MLP head: thread per graph ----------------
__global__ void k_head(const float* __restrict__ Wh1, const float* __restrict__ bh1,
                       const float* __restrict__ Wh2, const float* __restrict__ bh2,
                       float* __restrict__ out) {
    int g = blockIdx.x * blockDim.x + threadIdx.x;
    if (g >= GG) return;
    float cnt = fmaxf(g_cnt[g], 1.0f);
    float invc = 1.f / cnt;
    float p[C2];
    #pragma unroll
    for (int c = 0; c < C2; c++) p[c] = g_pool[g * C2 + c] * invc;
    float o = bh2[0];
    for (int j = 0; j < 64; j++) {
        float a = bh1[j];
        #pragma unroll
        for (int c = 0; c < C2; c++) a += p[c] * Wh1[c * 64 + j];
        a = fmaxf(a, 0.f);
        o += a * Wh2[j];
    }
    out[g] = o;
}

// ---------------- launch ----------------
extern "C" void kernel_launch(void* const* d_in, const int* in_sizes, int n_in,
                              void* d_out, int out_size) {
    const float* x     = (const float*)d_in[0];
    const int*   ei    = (const int*)d_in[1];     // int32 (JAX x64 disabled)
    const int*   batch = (const int*)d_in[2];     // int32
    const float* W1   = (const float*)d_in[3];
    const float* as1  = (const float*)d_in[4];
    const float* ad1  = (const float*)d_in[5];
    const float* b1   = (const float*)d_in[6];
    const float* W2   = (const float*)d_in[7];
    const float* as2  = (const float*)d_in[8];
    const float* ad2  = (const float*)d_in[9];
    const float* b2   = (const float*)d_in[10];
    const float* Wh1  = (const float*)d_in[11];
    const float* bh1  = (const float*)d_in[12];
    const float* Wh2  = (const float*)d_in[13];
    const float* bh2  = (const float*)d_in[14];
    float* out = (float*)d_out;

    k_init<<<(NN + 255) / 256, 256>>>();
    k_degree<<<(EE + 255) / 256, 256>>>(ei);
    k_scan<<<1, 1024>>>();
    k_cursor<<<(NN + 255) / 256, 256>>>();
    k_scatter<<<(ET + 255) / 256, 256>>>(ei);
    k_gemm1<<<(NN + 63) / 64, 256>>>(x, W1, as1, ad1);
    k_edge1<<<(NN + 7) / 8, 256>>>(b1);
    k_gemm2<<<(NN + 255) / 256, 256>>>(W2, as2, ad2);
    k_edge2<<<(NN + 7) / 8, 256>>>(b2, batch);
    k_head<<<1, 128>>>(Wh1, bh1, Wh2, bh2, out);
}

// round 3
// speedup vs baseline: 1.2672x; 1.2672x over previous
#include <cuda_runtime.h>
#include <cuda_bf16.h>
#include <math.h>

#define NN 50000
#define EE 1600000
#define ET (EE + NN)     // edges + self loops
#define GG 100
#define IN_CH 16
#define H1 4
#define C1 32
#define D1 (H1*C1)       // 128
#define C2 32
#define NEG 0.2f

// ---------------- scratch (static device globals; no allocation) ----------------
__device__ int   g_deg[NN];
__device__ int   g_rowptr[NN + 1];
__device__ int   g_cursor[NN];
__device__ int   g_csrsrc[ET];
__device__ __align__(16) float g_alpha[ET * H1];          // unnormalized exp weights
__device__ __align__(16) float g_h1[NN * D1];
__device__ __align__(16) float g_as1[NN * H1];
__device__ __align__(16) float g_ad1[NN * H1];
__device__ __align__(16) float g_out1[NN * D1];
__device__ __align__(16) float g_h2[NN * C2];
__device__ float g_as2[NN];
__device__ float g_ad2[NN];
__device__ float g_pool[GG * C2];
__device__ float g_cnt[GG];

// ---------------- init ----------------
__global__ void k_init() {
    int i = blockIdx.x * blockDim.x + threadIdx.x;
    if (i < NN) g_deg[i] = 1;           // self loop
    if (i < GG * C2) g_pool[i] = 0.f;
    if (i < GG) g_cnt[i] = 0.f;
}

// ---------------- degree count ----------------
__global__ void k_degree(const int* __restrict__ ei) {
    int e = blockIdx.x * blockDim.x + threadIdx.x;
    if (e >= EE) return;
    atomicAdd(&g_deg[ei[EE + e]], 1);
}

// ---------------- single-block exclusive scan (also fills cursor) ----------------
__global__ void k_scan() {
    __shared__ int warp_sums[32];
    __shared__ int carry_s;
    int t = threadIdx.x;
    int lane = t & 31, warp = t >> 5;
    if (t == 0) carry_s = 0;
    __syncthreads();
    for (int base = 0; base < NN; base += 1024) {
        int idx = base + t;
        int v = (idx < NN) ? g_deg[idx] : 0;
        int incl = v;
        #pragma unroll
        for (int off = 1; off < 32; off <<= 1) {
            int n = __shfl_up_sync(0xffffffffu, incl, off);
            if (lane >= off) incl += n;
        }
        if (lane == 31) warp_sums[warp] = incl;
        __syncthreads();
        if (warp == 0) {
            int ws = warp_sums[lane];
            int wincl = ws;
            #pragma unroll
            for (int off = 1; off < 32; off <<= 1) {
                int n = __shfl_up_sync(0xffffffffu, wincl, off);
                if (lane >= off) wincl += n;
            }
            warp_sums[lane] = wincl - ws;
        }
        __syncthreads();
        int carry = carry_s;
        int total_pos = carry + warp_sums[warp] + incl;
        if (idx < NN) {
            int excl = total_pos - v;
            g_rowptr[idx] = excl;
            g_cursor[idx] = excl;
        }
        __syncthreads();
        if (t == 1023) carry_s = total_pos;
        __syncthreads();
    }
    if (t == 0) g_rowptr[NN] = carry_s;
}

// ---------------- scatter edges into CSR (by dst), incl. self loops ----------------
__global__ void k_scatter(const int* __restrict__ ei) {
    int idx = blockIdx.x * blockDim.x + threadIdx.x;
    if (idx >= ET) return;
    int src, dst;
    if (idx < EE) { src = ei[idx]; dst = ei[EE + idx]; }
    else          { src = idx - EE; dst = src; }
    int slot = atomicAdd(&g_cursor[dst], 1);
    g_csrsrc[slot] = src;
}

// ---------------- GEMM1 + attention logits ----------------
__global__ void k_gemm1(const float* __restrict__ x,
                        const float* __restrict__ W1,
                        const float* __restrict__ as_w,
                        const float* __restrict__ ad_w) {
    __shared__ float sW[IN_CH * D1];
    __shared__ float sAs[H1 * C1];
    __shared__ float sAd[H1 * C1];
    int t = threadIdx.x;
    for (int i = t; i < IN_CH * D1; i += 256) sW[i] = W1[i];
    if (t < H1 * C1) { sAs[t] = as_w[t]; sAd[t] = ad_w[t]; }
    __syncthreads();

    int warp = t >> 5, lane = t & 31;
    int h = warp & 3;
    int n = blockIdx.x * 64 + (warp >> 2) * 32 + lane;
    if (n >= NN) return;

    float xv[16];
    const float4* xp = (const float4*)(x + (size_t)n * IN_CH);
    #pragma unroll
    for (int i = 0; i < 4; i++) {
        float4 r = xp[i];
        xv[4*i]=r.x; xv[4*i+1]=r.y; xv[4*i+2]=r.z; xv[4*i+3]=r.w;
    }
    float acc[C1];
    #pragma unroll
    for (int c = 0; c < C1; c++) acc[c] = 0.f;
    #pragma unroll
    for (int k = 0; k < IN_CH; k++) {
        float xk = xv[k];
        const float* wrow = sW + k * D1 + h * C1;
        #pragma unroll
        for (int c = 0; c < C1; c++) acc[c] += xk * wrow[c];
    }
    float asum = 0.f, dsum = 0.f;
    #pragma unroll
    for (int c = 0; c < C1; c++) { asum += acc[c] * sAs[h*C1+c]; dsum += acc[c] * sAd[h*C1+c]; }
    g_as1[n * H1 + h] = asum;
    g_ad1[n * H1 + h] = dsum;
    float4* hp = (float4*)(g_h1 + (size_t)n * D1 + h * C1);
    #pragma unroll
    for (int i = 0; i < 8; i++) hp[i] = make_float4(acc[4*i], acc[4*i+1], acc[4*i+2], acc[4*i+3]);
}

__device__ __forceinline__ float lrelu(float e) { return e > 0.f ? e : NEG * e; }
__device__ __forceinline__ float elu(float v)   { return v > 0.f ? v : expm1f(v); }

// ---------------- GAT layer 1: warp per dst node, 2 passes, no shuffle bcast ----------------
__global__ void k_edge1(const float* __restrict__ b1) {
    int gwarp = (blockIdx.x * blockDim.x + threadIdx.x) >> 5;
    int lane = threadIdx.x & 31;
    if (gwarp >= NN) return;
    int n = gwarp;
    int beg = g_rowptr[n], end = g_rowptr[n + 1];
    float4 ad = *(const float4*)(g_ad1 + n * 4);

    // Pass A: unnormalized exp weights -> g_alpha; accumulate sums
    float s0 = 0.f, s1 = 0.f, s2 = 0.f, s3 = 0.f;
    for (int i = beg + lane; i < end; i += 32) {
        int s = g_csrsrc[i];
        float4 as = *(const float4*)(g_as1 + s * 4);
        float e0 = __expf(lrelu(as.x + ad.x));
        float e1 = __expf(lrelu(as.y + ad.y));
        float e2 = __expf(lrelu(as.z + ad.z));
        float e3 = __expf(lrelu(as.w + ad.w));
        *(float4*)(g_alpha + (size_t)i * 4) = make_float4(e0, e1, e2, e3);
        s0 += e0; s1 += e1; s2 += e2; s3 += e3;
    }
    #pragma unroll
    for (int off = 16; off; off >>= 1) {
        s0 += __shfl_xor_sync(0xffffffffu, s0, off);
        s1 += __shfl_xor_sync(0xffffffffu, s1, off);
        s2 += __shfl_xor_sync(0xffffffffu, s2, off);
        s3 += __shfl_xor_sync(0xffffffffu, s3, off);
    }
    float i0 = 1.f / (s0 + 1e-16f), i1 = 1.f / (s1 + 1e-16f);
    float i2 = 1.f / (s2 + 1e-16f), i3 = 1.f / (s3 + 1e-16f);

    // Pass B: warp-uniform edge walk; broadcast loads + coalesced feature lines
    float acc0 = 0.f, acc1 = 0.f, acc2 = 0.f, acc3 = 0.f;
    int i = beg;
    for (; i + 4 <= end; i += 4) {
        int e0 = g_csrsrc[i],     e1 = g_csrsrc[i + 1];
        int e2 = g_csrsrc[i + 2], e3 = g_csrsrc[i + 3];
        float4 a0 = *(const float4*)(g_alpha + (size_t)(i    ) * 4);
        float4 a1 = *(const float4*)(g_alpha + (size_t)(i + 1) * 4);
        float4 a2 = *(const float4*)(g_alpha + (size_t)(i + 2) * 4);
        float4 a3 = *(const float4*)(g_alpha + (size_t)(i + 3) * 4);
        const float* p0 = g_h1 + (size_t)e0 * D1;
        const float* p1 = g_h1 + (size_t)e1 * D1;
        const float* p2 = g_h1 + (size_t)e2 * D1;
        const float* p3 = g_h1 + (size_t)e3 * D1;
        acc0 += a0.x * p0[lane]      + a1.x * p1[lane]      + a2.x * p2[lane]      + a3.x * p3[lane];
        acc1 += a0.y * p0[32 + lane] + a1.y * p1[32 + lane] + a2.y * p2[32 + lane] + a3.y * p3[32 + lane];
        acc2 += a0.z * p0[64 + lane] + a1.z * p1[64 + lane] + a2.z * p2[64 + lane] + a3.z * p3[64 + lane];
        acc3 += a0.w * p0[96 + lane] + a1.w * p1[96 + lane] + a2.w * p2[96 + lane] + a3.w * p3[96 + lane];
    }
    for (; i < end; i++) {
        int e = g_csrsrc[i];
        float4 a = *(const float4*)(g_alpha + (size_t)i * 4);
        const float* p = g_h1 + (size_t)e * D1;
        acc0 += a.x * p[lane];
        acc1 += a.y * p[32 + lane];
        acc2 += a.z * p[64 + lane];
        acc3 += a.w * p[96 + lane];
    }
    float* op = g_out1 + (size_t)n * D1;
    op[lane]      = elu(acc0 * i0 + b1[lane]);
    op[32 + lane] = elu(acc1 * i1 + b1[32 + lane]);
    op[64 + lane] = elu(acc2 * i2 + b1[64 + lane]);
    op[96 + lane] = elu(acc3 * i3 + b1[96 + lane]);
}

// ---------------- GEMM2 + attention logits (thread per node) ----------------
__global__ void k_gemm2(const float* __restrict__ W2,
                        const float* __restrict__ as_w,
                        const float* __restrict__ ad_w) {
    __shared__ float sW[D1 * C2];
    __shared__ float sAs[C2], sAd[C2];
    int t = threadIdx.x;
    for (int i = t; i < D1 * C2; i += 256) sW[i] = W2[i];
    if (t < C2) { sAs[t] = as_w[t]; sAd[t] = ad_w[t]; }
    __syncthreads();
    int n = blockIdx.x * blockDim.x + t;
    if (n >= NN) return;

    float acc[C2];
    #pragma unroll
    for (int c = 0; c < C2; c++) acc[c] = 0.f;
    const float4* xp = (const float4*)(g_out1 + (size_t)n * D1);
    for (int k4 = 0; k4 < 32; k4++) {
        float4 xv = xp[k4];
        const float* w0 = sW + (k4 * 4) * C2;
        #pragma unroll
        for (int c = 0; c < C2; c++) {
            acc[c] += xv.x * w0[c] + xv.y * w0[C2 + c] + xv.z * w0[2*C2 + c] + xv.w * w0[3*C2 + c];
        }
    }
    float asum = 0.f, dsum = 0.f;
    #pragma unroll
    for (int c = 0; c < C2; c++) { asum += acc[c] * sAs[c]; dsum += acc[c] * sAd[c]; }
    g_as2[n] = asum;
    g_ad2[n] = dsum;
    float4* hp = (float4*)(g_h2 + (size_t)n * C2);
    #pragma unroll
    for (int i = 0; i < 8; i++) hp[i] = make_float4(acc[4*i], acc[4*i+1], acc[4*i+2], acc[4*i+3]);
}

// ---------------- GAT layer 2 + pooling: warp per dst node ----------------
__global__ void k_edge2(const float* __restrict__ b2,
                        const int* __restrict__ batch) {
    int gwarp = (blockIdx.x * blockDim.x + threadIdx.x) >> 5;
    int lane = threadIdx.x & 31;
    if (gwarp >= NN) return;
    int n = gwarp;
    int beg = g_rowptr[n], end = g_rowptr[n + 1];
    float ad = g_ad2[n];

    float ssum = 0.f;
    for (int i = beg + lane; i < end; i += 32) {
        int s = g_csrsrc[i];
        float e = __expf(lrelu(g_as2[s] + ad));
        g_alpha[i] = e;
        ssum += e;
    }
    #pragma unroll
    for (int off = 16; off; off >>= 1) ssum += __shfl_xor_sync(0xffffffffu, ssum, off);
    float inv = 1.f / (ssum + 1e-16f);

    float acc = 0.f;
    int i = beg;
    for (; i + 4 <= end; i += 4) {
        int e0 = g_csrsrc[i],     e1 = g_csrsrc[i + 1];
        int e2 = g_csrsrc[i + 2], e3 = g_csrsrc[i + 3];
        float a0 = g_alpha[i],     a1 = g_alpha[i + 1];
        float a2 = g_alpha[i + 2], a3 = g_alpha[i + 3];
        acc += a0 * g_h2[(size_t)e0 * C2 + lane]
             + a1 * g_h2[(size_t)e1 * C2 + lane]
             + a2 * g_h2[(size_t)e2 * C2 + lane]
             + a3 * g_h2[(size_t)e3 * C2 + lane];
    }
    for (; i < end; i++) {
        acc += g_alpha[i] * g_h2[(size_t)g_csrsrc[i] * C2 + lane];
    }
    float v = elu(acc * inv + b2[lane]);
    int gid = batch[n];
    atomicAdd(&g_pool[gid * C2 + lane], v);
    if (lane == 0) atomicAdd(&g_cnt[gid], 1.0f);
}

// ---------------- MLP head: thread per graph ----------------
__global__ void k_head(const float* __restrict__ Wh1, const float* __restrict__ bh1,
                       const float* __restrict__ Wh2, const float* __restrict__ bh2,
                       float* __restrict__ out) {
    int g = blockIdx.x * blockDim.x + threadIdx.x;
    if (g >= GG) return;
    float cnt = fmaxf(g_cnt[g], 1.0f);
    float invc = 1.f / cnt;
    float p[C2];
    #pragma unroll
    for (int c = 0; c < C2; c++) p[c] = g_pool[g * C2 + c] * invc;
    float o = bh2[0];
    for (int j = 0; j < 64; j++) {
        float a = bh1[j];
        #pragma unroll
        for (int c = 0; c < C2; c++) a += p[c] * Wh1[c * 64 + j];
        a = fmaxf(a, 0.f);
        o += a * Wh2[j];
    }
    out[g] = o;
}

// ---------------- launch ----------------
extern "C" void kernel_launch(void* const* d_in, const int* in_sizes, int n_in,
                              void* d_out, int out_size) {
    const float* x     = (const float*)d_in[0];
    const int*   ei    = (const int*)d_in[1];
    const int*   batch = (const int*)d_in[2];
    const float* W1   = (const float*)d_in[3];
    const float* as1  = (const float*)d_in[4];
    const float* ad1  = (const float*)d_in[5];
    const float* b1   = (const float*)d_in[6];
    const float* W2   = (const float*)d_in[7];
    const float* as2  = (const float*)d_in[8];
    const float* ad2  = (const float*)d_in[9];
    const float* b2   = (const float*)d_in[10];
    const float* Wh1  = (const float*)d_in[11];
    const float* bh1  = (const float*)d_in[12];
    const float* Wh2  = (const float*)d_in[13];
    const float* bh2  = (const float*)d_in[14];
    float* out = (float*)d_out;

    k_init<<<(NN + 255) / 256, 256>>>();
    k_degree<<<(EE + 255) / 256, 256>>>(ei);
    k_scan<<<1, 1024>>>();
    k_scatter<<<(ET + 255) / 256, 256>>>(ei);
    k_gemm1<<<(NN + 63) / 64, 256>>>(x, W1, as1, ad1);
    k_edge1<<<(NN + 7) / 8, 256>>>(b1);
    k_gemm2<<<(NN + 255) / 256, 256>>>(W2, as2, ad2);
    k_edge2<<<(NN + 7) / 8, 256>>>(b2, batch);
    k_head<<<1, 128>>>(Wh1, bh1, Wh2, bh2, out);
}

// round 4
// speedup vs baseline: 1.3546x; 1.0690x over previous
#include <cuda_runtime.h>
#include <cuda_fp16.h>
#include <math.h>

#define NN 50000
#define EE 1600000
#define ET (EE + NN)     // edges + self loops
#define GG 100
#define IN_CH 16
#define H1 4
#define C1 32
#define D1 (H1*C1)       // 128
#define C2 32
#define NEG 0.2f

// ---------------- scratch (static device globals; no allocation) ----------------
__device__ int   g_deg[NN];
__device__ int   g_rowptr[NN + 1];
__device__ int   g_cursor[NN];
__device__ int   g_csrsrc[ET];
__device__ __align__(16) float  g_alpha[ET * H1];     // unnormalized exp weights
__device__ __align__(16) __half g_h1h[NN * D1];       // fp16 features, layer 1
__device__ __align__(16) float  g_as1[NN * H1];
__device__ __align__(16) float  g_ad1[NN * H1];
__device__ __align__(16) float  g_out1[NN * D1];
__device__ __align__(16) float  g_h2[NN * C2];
__device__ float g_as2[NN];
__device__ float g_ad2[NN];
__device__ float g_pool[GG * C2];
__device__ float g_cnt[GG];

// ---------------- init ----------------
__global__ void k_init() {
    int i = blockIdx.x * blockDim.x + threadIdx.x;
    if (i < NN) g_deg[i] = 1;           // self loop
    if (i < GG * C2) g_pool[i] = 0.f;
    if (i < GG) g_cnt[i] = 0.f;
}

// ---------------- degree count ----------------
__global__ void k_degree(const int* __restrict__ ei) {
    int e = blockIdx.x * blockDim.x + threadIdx.x;
    if (e >= EE) return;
    atomicAdd(&g_deg[ei[EE + e]], 1);
}

// ---------------- single-block exclusive scan (also fills cursor) ----------------
__global__ void k_scan() {
    __shared__ int warp_sums[32];
    __shared__ int carry_s;
    int t = threadIdx.x;
    int lane = t & 31, warp = t >> 5;
    if (t == 0) carry_s = 0;
    __syncthreads();
    for (int base = 0; base < NN; base += 1024) {
        int idx = base + t;
        int v = (idx < NN) ? g_deg[idx] : 0;
        int incl = v;
        #pragma unroll
        for (int off = 1; off < 32; off <<= 1) {
            int n = __shfl_up_sync(0xffffffffu, incl, off);
            if (lane >= off) incl += n;
        }
        if (lane == 31) warp_sums[warp] = incl;
        __syncthreads();
        if (warp == 0) {
            int ws = warp_sums[lane];
            int wincl = ws;
            #pragma unroll
            for (int off = 1; off < 32; off <<= 1) {
                int n = __shfl_up_sync(0xffffffffu, wincl, off);
                if (lane >= off) wincl += n;
            }
            warp_sums[lane] = wincl - ws;
        }
        __syncthreads();
        int carry = carry_s;
        int total_pos = carry + warp_sums[warp] + incl;
        if (idx < NN) {
            int excl = total_pos - v;
            g_rowptr[idx] = excl;
            g_cursor[idx] = excl;
        }
        __syncthreads();
        if (t == 1023) carry_s = total_pos;
        __syncthreads();
    }
    if (t == 0) g_rowptr[NN] = carry_s;
}

// ---------------- scatter edges into CSR (by dst), incl. self loops ----------------
__global__ void k_scatter(const int* __restrict__ ei) {
    int idx = blockIdx.x * blockDim.x + threadIdx.x;
    if (idx >= ET) return;
    int src, dst;
    if (idx < EE) { src = ei[idx]; dst = ei[EE + idx]; }
    else          { src = idx - EE; dst = src; }
    int slot = atomicAdd(&g_cursor[dst], 1);
    g_csrsrc[slot] = src;
}

// ---------------- GEMM1 + attention logits ----------------
// warp handles (nodegroup, head): each thread computes one node's one head (32 ch).
__global__ void k_gemm1(const float* __restrict__ x,
                        const float* __restrict__ W1,
                        const float* __restrict__ as_w,
                        const float* __restrict__ ad_w) {
    __shared__ float sW[IN_CH * D1];
    __shared__ float sAs[H1 * C1];
    __shared__ float sAd[H1 * C1];
    int t = threadIdx.x;
    for (int i = t; i < IN_CH * D1; i += 256) sW[i] = W1[i];
    if (t < H1 * C1) { sAs[t] = as_w[t]; sAd[t] = ad_w[t]; }
    __syncthreads();

    int warp = t >> 5, lane = t & 31;
    int h = warp & 3;
    int n = blockIdx.x * 64 + (warp >> 2) * 32 + lane;
    if (n >= NN) return;

    float xv[16];
    const float4* xp = (const float4*)(x + (size_t)n * IN_CH);
    #pragma unroll
    for (int i = 0; i < 4; i++) {
        float4 r = xp[i];
        xv[4*i]=r.x; xv[4*i+1]=r.y; xv[4*i+2]=r.z; xv[4*i+3]=r.w;
    }
    float acc[C1];
    #pragma unroll
    for (int c = 0; c < C1; c++) acc[c] = 0.f;
    #pragma unroll
    for (int k = 0; k < IN_CH; k++) {
        float xk = xv[k];
        const float* wrow = sW + k * D1 + h * C1;
        #pragma unroll
        for (int c = 0; c < C1; c++) acc[c] += xk * wrow[c];
    }
    float asum = 0.f, dsum = 0.f;
    #pragma unroll
    for (int c = 0; c < C1; c++) { asum += acc[c] * sAs[h*C1+c]; dsum += acc[c] * sAd[h*C1+c]; }
    g_as1[n * H1 + h] = asum;
    g_ad1[n * H1 + h] = dsum;
    // store fp16 features: 32 ch -> 16 half2 -> 4 uint4 (64B contiguous per thread)
    uint4 pk[4];
    unsigned* pu = (unsigned*)pk;
    #pragma unroll
    for (int i = 0; i < 16; i++) {
        __half2 hh = __floats2half2_rn(acc[2*i], acc[2*i+1]);
        pu[i] = *(unsigned*)&hh;
    }
    uint4* hp = (uint4*)(g_h1h + (size_t)n * D1 + h * C1);
    #pragma unroll
    for (int i = 0; i < 4; i++) hp[i] = pk[i];
}

__device__ __forceinline__ float lrelu(float e) { return e > 0.f ? e : NEG * e; }
__device__ __forceinline__ float elu(float v)   { return v > 0.f ? v : expm1f(v); }

__device__ __forceinline__ float sel4(float4 a, int q) {
    float w = a.x;
    w = (q == 1) ? a.y : w;
    w = (q == 2) ? a.z : w;
    w = (q == 3) ? a.w : w;
    return w;
}

// ---------------- GAT layer 1: warp per dst node ----------------
// lane owns channels [4l, 4l+3] (head = l>>3); 1 LDG.64 per edge.
__global__ void k_edge1(const float* __restrict__ b1) {
    int gwarp = (blockIdx.x * blockDim.x + threadIdx.x) >> 5;
    int lane = threadIdx.x & 31;
    if (gwarp >= NN) return;
    int n = gwarp;
    int beg = g_rowptr[n], end = g_rowptr[n + 1];
    float4 ad = *(const float4*)(g_ad1 + n * 4);

    // Pass A: unnormalized exp weights -> g_alpha; accumulate per-head sums
    float s0 = 0.f, s1 = 0.f, s2 = 0.f, s3 = 0.f;
    for (int i = beg + lane; i < end; i += 32) {
        int s = g_csrsrc[i];
        float4 as = *(const float4*)(g_as1 + s * 4);
        float e0 = __expf(lrelu(as.x + ad.x));
        float e1 = __expf(lrelu(as.y + ad.y));
        float e2 = __expf(lrelu(as.z + ad.z));
        float e3 = __expf(lrelu(as.w + ad.w));
        *(float4*)(g_alpha + (size_t)i * 4) = make_float4(e0, e1, e2, e3);
        s0 += e0; s1 += e1; s2 += e2; s3 += e3;
    }
    #pragma unroll
    for (int off = 16; off; off >>= 1) {
        s0 += __shfl_xor_sync(0xffffffffu, s0, off);
        s1 += __shfl_xor_sync(0xffffffffu, s1, off);
        s2 += __shfl_xor_sync(0xffffffffu, s2, off);
        s3 += __shfl_xor_sync(0xffffffffu, s3, off);
    }
    int q = lane >> 3;                       // head owned by this lane
    float inv = sel4(make_float4(1.f/(s0+1e-16f), 1.f/(s1+1e-16f),
                                 1.f/(s2+1e-16f), 1.f/(s3+1e-16f)), q);

    // Pass B: warp-uniform edge walk, 8-deep pipeline, 1 LDG.64 feature per edge
    float a0 = 0.f, a1 = 0.f, a2 = 0.f, a3 = 0.f;
    const __half* hbase = g_h1h;
    int laneoff = lane * 4;
    int i = beg;
    for (; i + 8 <= end; i += 8) {
        int sidx[8];
        #pragma unroll
        for (int j = 0; j < 8; j++) sidx[j] = g_csrsrc[i + j];
        float4 al[8];
        #pragma unroll
        for (int j = 0; j < 8; j++) al[j] = *(const float4*)(g_alpha + (size_t)(i + j) * 4);
        #pragma unroll
        for (int j = 0; j < 8; j++) {
            uint2 pv = *(const uint2*)(hbase + (size_t)sidx[j] * D1 + laneoff);
            float w = sel4(al[j], q);
            __half2 h01 = *(__half2*)&pv.x;
            __half2 h23 = *(__half2*)&pv.y;
            float2 f01 = __half22float2(h01);
            float2 f23 = __half22float2(h23);
            a0 += w * f01.x; a1 += w * f01.y;
            a2 += w * f23.x; a3 += w * f23.y;
        }
    }
    for (; i < end; i++) {
        int s = g_csrsrc[i];
        float4 alx = *(const float4*)(g_alpha + (size_t)i * 4);
        uint2 pv = *(const uint2*)(hbase + (size_t)s * D1 + laneoff);
        float w = sel4(alx, q);
        __half2 h01 = *(__half2*)&pv.x;
        __half2 h23 = *(__half2*)&pv.y;
        float2 f01 = __half22float2(h01);
        float2 f23 = __half22float2(h23);
        a0 += w * f01.x; a1 += w * f01.y;
        a2 += w * f23.x; a3 += w * f23.y;
    }
    const float4 bv = *(const float4*)(b1 + laneoff);
    float4 ov;
    ov.x = elu(a0 * inv + bv.x);
    ov.y = elu(a1 * inv + bv.y);
    ov.z = elu(a2 * inv + bv.z);
    ov.w = elu(a3 * inv + bv.w);
    *(float4*)(g_out1 + (size_t)n * D1 + laneoff) = ov;
}

// ---------------- GEMM2 + attention logits (thread per node) ----------------
__global__ void k_gemm2(const float* __restrict__ W2,
                        const float* __restrict__ as_w,
                        const float* __restrict__ ad_w) {
    __shared__ float sW[D1 * C2];
    __shared__ float sAs[C2], sAd[C2];
    int t = threadIdx.x;
    for (int i = t; i < D1 * C2; i += 256) sW[i] = W2[i];
    if (t < C2) { sAs[t] = as_w[t]; sAd[t] = ad_w[t]; }
    __syncthreads();
    int n = blockIdx.x * blockDim.x + t;
    if (n >= NN) return;

    float acc[C2];
    #pragma unroll
    for (int c = 0; c < C2; c++) acc[c] = 0.f;
    const float4* xp = (const float4*)(g_out1 + (size_t)n * D1);
    for (int k4 = 0; k4 < 32; k4++) {
        float4 xv = xp[k4];
        const float* w0 = sW + (k4 * 4) * C2;
        #pragma unroll
        for (int c = 0; c < C2; c++) {
            acc[c] += xv.x * w0[c] + xv.y * w0[C2 + c] + xv.z * w0[2*C2 + c] + xv.w * w0[3*C2 + c];
        }
    }
    float asum = 0.f, dsum = 0.f;
    #pragma unroll
    for (int c = 0; c < C2; c++) { asum += acc[c] * sAs[c]; dsum += acc[c] * sAd[c]; }
    g_as2[n] = asum;
    g_ad2[n] = dsum;
    float4* hp = (float4*)(g_h2 + (size_t)n * C2);
    #pragma unroll
    for (int i = 0; i < 8; i++) hp[i] = make_float4(acc[4*i], acc[4*i+1], acc[4*i+2], acc[4*i+3]);
}

// ---------------- GAT layer 2 + pooling: warp per dst node ----------------
__global__ void k_edge2(const float* __restrict__ b2,
                        const int* __restrict__ batch) {
    int gwarp = (blockIdx.x * blockDim.x + threadIdx.x) >> 5;
    int lane = threadIdx.x & 31;
    if (gwarp >= NN) return;
    int n = gwarp;
    int beg = g_rowptr[n], end = g_rowptr[n + 1];
    float ad = g_ad2[n];

    float ssum = 0.f;
    for (int i = beg + lane; i < end; i += 32) {
        int s = g_csrsrc[i];
        float e = __expf(lrelu(g_as2[s] + ad));
        g_alpha[i] = e;
        ssum += e;
    }
    #pragma unroll
    for (int off = 16; off; off >>= 1) ssum += __shfl_xor_sync(0xffffffffu, ssum, off);
    float inv = 1.f / (ssum + 1e-16f);

    float acc = 0.f;
    int i = beg;
    for (; i + 8 <= end; i += 8) {
        int sidx[8];
        #pragma unroll
        for (int j = 0; j < 8; j++) sidx[j] = g_csrsrc[i + j];
        float al[8];
        #pragma unroll
        for (int j = 0; j < 8; j++) al[j] = g_alpha[i + j];
        #pragma unroll
        for (int j = 0; j < 8; j++)
            acc += al[j] * g_h2[(size_t)sidx[j] * C2 + lane];
    }
    for (; i < end; i++) {
        acc += g_alpha[i] * g_h2[(size_t)g_csrsrc[i] * C2 + lane];
    }
    float v = elu(acc * inv + b2[lane]);
    int gid = batch[n];
    atomicAdd(&g_pool[gid * C2 + lane], v);
    if (lane == 0) atomicAdd(&g_cnt[gid], 1.0f);
}

// ---------------- MLP head: thread per graph ----------------
__global__ void k_head(const float* __restrict__ Wh1, const float* __restrict__ bh1,
                       const float* __restrict__ Wh2, const float* __restrict__ bh2,
                       float* __restrict__ out) {
    int g = blockIdx.x * blockDim.x + threadIdx.x;
    if (g >= GG) return;
    float cnt = fmaxf(g_cnt[g], 1.0f);
    float invc = 1.f / cnt;
    float p[C2];
    #pragma unroll
    for (int c = 0; c < C2; c++) p[c] = g_pool[g * C2 + c] * invc;
    float o = bh2[0];
    for (int j = 0; j < 64; j++) {
        float a = bh1[j];
        #pragma unroll
        for (int c = 0; c < C2; c++) a += p[c] * Wh1[c * 64 + j];
        a = fmaxf(a, 0.f);
        o += a * Wh2[j];
    }
    out[g] = o;
}

// ---------------- launch ----------------
extern "C" void kernel_launch(void* const* d_in, const int* in_sizes, int n_in,
                              void* d_out, int out_size) {
    const float* x     = (const float*)d_in[0];
    const int*   ei    = (const int*)d_in[1];
    const int*   batch = (const int*)d_in[2];
    const float* W1   = (const float*)d_in[3];
    const float* as1  = (const float*)d_in[4];
    const float* ad1  = (const float*)d_in[5];
    const float* b1   = (const float*)d_in[6];
    const float* W2   = (const float*)d_in[7];
    const float* as2  = (const float*)d_in[8];
    const float* ad2  = (const float*)d_in[9];
    const float* b2   = (const float*)d_in[10];
    const float* Wh1  = (const float*)d_in[11];
    const float* bh1  = (const float*)d_in[12];
    const float* Wh2  = (const float*)d_in[13];
    const float* bh2  = (const float*)d_in[14];
    float* out = (float*)d_out;

    k_init<<<(NN + 255) / 256, 256>>>();
    k_degree<<<(EE + 255) / 256, 256>>>(ei);
    k_scan<<<1, 1024>>>();
    k_scatter<<<(ET + 255) / 256, 256>>>(ei);
    k_gemm1<<<(NN + 63) / 64, 256>>>(x, W1, as1, ad1);
    k_edge1<<<(NN + 7) / 8, 256>>>(b1);
    k_gemm2<<<(NN + 255) / 256, 256>>>(W2, as2, ad2);
    k_edge2<<<(NN + 7) / 8, 256>>>(b2, batch);
    k_head<<<1, 128>>>(Wh1, bh1, Wh2, bh2, out);
}

// round 5
// speedup vs baseline: 1.3979x; 1.0320x over previous
#include <cuda_runtime.h>
#include <cuda_fp16.h>
#include <math.h>

#define NN 50000
#define EE 1600000
#define ET (EE + NN)     // edges + self loops
#define GG 100
#define IN_CH 16
#define H1 4
#define C1 32
#define D1 (H1*C1)       // 128
#define C2 32
#define NEG 0.2f

// ---------------- scratch ----------------
__device__ int   g_deg[NN];
__device__ int   g_rowptr[NN + 1];
__device__ int   g_cursor[NN];
__device__ __align__(16) int g_csrsrc[ET];
__device__ __align__(16) __half g_h1h[NN * D1];       // fp16 features, layer 1
__device__ __align__(16) float  g_as1[NN * H1];
__device__ __align__(16) float  g_ad1[NN * H1];
__device__ __align__(16) float  g_out1[NN * D1];
__device__ __align__(16) float  g_h2[NN * C2];
__device__ float g_as2[NN];
__device__ float g_ad2[NN];
__device__ float g_pool[GG * C2];
__device__ float g_cnt[GG];

// ---------------- init ----------------
__global__ void k_init() {
    int i = blockIdx.x * blockDim.x + threadIdx.x;
    if (i < NN) g_deg[i] = 1;           // self loop
    if (i < GG * C2) g_pool[i] = 0.f;
    if (i < GG) g_cnt[i] = 0.f;
}

// ---------------- degree count ----------------
__global__ void k_degree(const int* __restrict__ ei) {
    int e = blockIdx.x * blockDim.x + threadIdx.x;
    if (e >= EE) return;
    atomicAdd(&g_deg[ei[EE + e]], 1);
}

// ---------------- single-block exclusive scan (also fills cursor) ----------------
__global__ void k_scan() {
    __shared__ int warp_sums[32];
    __shared__ int carry_s;
    int t = threadIdx.x;
    int lane = t & 31, warp = t >> 5;
    if (t == 0) carry_s = 0;
    __syncthreads();
    for (int base = 0; base < NN; base += 1024) {
        int idx = base + t;
        int v = (idx < NN) ? g_deg[idx] : 0;
        int incl = v;
        #pragma unroll
        for (int off = 1; off < 32; off <<= 1) {
            int n = __shfl_up_sync(0xffffffffu, incl, off);
            if (lane >= off) incl += n;
        }
        if (lane == 31) warp_sums[warp] = incl;
        __syncthreads();
        if (warp == 0) {
            int ws = warp_sums[lane];
            int wincl = ws;
            #pragma unroll
            for (int off = 1; off < 32; off <<= 1) {
                int n = __shfl_up_sync(0xffffffffu, wincl, off);
                if (lane >= off) wincl += n;
            }
            warp_sums[lane] = wincl - ws;
        }
        __syncthreads();
        int carry = carry_s;
        int total_pos = carry + warp_sums[warp] + incl;
        if (idx < NN) {
            int excl = total_pos - v;
            g_rowptr[idx] = excl;
            g_cursor[idx] = excl;
        }
        __syncthreads();
        if (t == 1023) carry_s = total_pos;
        __syncthreads();
    }
    if (t == 0) g_rowptr[NN] = carry_s;
}

// ---------------- scatter edges into CSR (by dst), incl. self loops ----------------
__global__ void k_scatter(const int* __restrict__ ei) {
    int idx = blockIdx.x * blockDim.x + threadIdx.x;
    if (idx >= ET) return;
    int src, dst;
    if (idx < EE) { src = ei[idx]; dst = ei[EE + idx]; }
    else          { src = idx - EE; dst = src; }
    int slot = atomicAdd(&g_cursor[dst], 1);
    g_csrsrc[slot] = src;
}

// ---------------- GEMM1 + attention logits ----------------
__global__ void k_gemm1(const float* __restrict__ x,
                        const float* __restrict__ W1,
                        const float* __restrict__ as_w,
                        const float* __restrict__ ad_w) {
    __shared__ float sW[IN_CH * D1];
    __shared__ float sAs[H1 * C1];
    __shared__ float sAd[H1 * C1];
    int t = threadIdx.x;
    for (int i = t; i < IN_CH * D1; i += 256) sW[i] = W1[i];
    if (t < H1 * C1) { sAs[t] = as_w[t]; sAd[t] = ad_w[t]; }
    __syncthreads();

    int warp = t >> 5, lane = t & 31;
    int h = warp & 3;
    int n = blockIdx.x * 64 + (warp >> 2) * 32 + lane;
    if (n >= NN) return;

    float xv[16];
    const float4* xp = (const float4*)(x + (size_t)n * IN_CH);
    #pragma unroll
    for (int i = 0; i < 4; i++) {
        float4 r = xp[i];
        xv[4*i]=r.x; xv[4*i+1]=r.y; xv[4*i+2]=r.z; xv[4*i+3]=r.w;
    }
    float acc[C1];
    #pragma unroll
    for (int c = 0; c < C1; c++) acc[c] = 0.f;
    #pragma unroll
    for (int k = 0; k < IN_CH; k++) {
        float xk = xv[k];
        const float* wrow = sW + k * D1 + h * C1;
        #pragma unroll
        for (int c = 0; c < C1; c++) acc[c] += xk * wrow[c];
    }
    float asum = 0.f, dsum = 0.f;
    #pragma unroll
    for (int c = 0; c < C1; c++) { asum += acc[c] * sAs[h*C1+c]; dsum += acc[c] * sAd[h*C1+c]; }
    g_as1[n * H1 + h] = asum;
    g_ad1[n * H1 + h] = dsum;
    uint4 pk[4];
    unsigned* pu = (unsigned*)pk;
    #pragma unroll
    for (int i = 0; i < 16; i++) {
        __half2 hh = __floats2half2_rn(acc[2*i], acc[2*i+1]);
        pu[i] = *(unsigned*)&hh;
    }
    uint4* hp = (uint4*)(g_h1h + (size_t)n * D1 + h * C1);
    #pragma unroll
    for (int i = 0; i < 4; i++) hp[i] = pk[i];
}

__device__ __forceinline__ float lrelu(float e) { return e > 0.f ? e : NEG * e; }
__device__ __forceinline__ float elu(float v)   { return v > 0.f ? v : (__expf(v) - 1.f); }

__device__ __forceinline__ float sel4(float4 a, int q) {
    float w = a.x;
    w = (q == 1) ? a.y : w;
    w = (q == 2) ? a.z : w;
    w = (q == 3) ? a.w : w;
    return w;
}

// ---------------- GAT layer 1: single-pass, warp per dst node ----------------
// lane owns channels [4l,4l+3] of head q=l>>3; warp-uniform edge walk.
__global__ void k_edge1(const float* __restrict__ b1) {
    int gwarp = (blockIdx.x * blockDim.x + threadIdx.x) >> 5;
    int lane = threadIdx.x & 31;
    if (gwarp >= NN) return;
    int n = gwarp;
    int beg = g_rowptr[n], end = g_rowptr[n + 1];
    int q = lane >> 3;
    float adq = sel4(*(const float4*)(g_ad1 + n * 4), q);
    int laneoff = lane * 4;
    const __half* hbase = g_h1h;

    float ssum = 0.f;
    float a0 = 0.f, a1 = 0.f, a2 = 0.f, a3 = 0.f;

    int i = beg;
    // scalar prologue to 16B-align csrsrc
    for (; i < end && (i & 3); i++) {
        int s = g_csrsrc[i];
        float e = __expf(lrelu(sel4(*(const float4*)(g_as1 + s * 4), q) + adq));
        ssum += e;
        uint2 pv = *(const uint2*)(hbase + (size_t)s * D1 + laneoff);
        float2 f01 = __half22float2(*(__half2*)&pv.x);
        float2 f23 = __half22float2(*(__half2*)&pv.y);
        a0 += e * f01.x; a1 += e * f01.y; a2 += e * f23.x; a3 += e * f23.y;
    }
    for (; i + 8 <= end; i += 8) {
        int4 c0 = *(const int4*)(g_csrsrc + i);
        int4 c1 = *(const int4*)(g_csrsrc + i + 4);
        int sidx[8] = {c0.x, c0.y, c0.z, c0.w, c1.x, c1.y, c1.z, c1.w};
        float asq[8];
        #pragma unroll
        for (int j = 0; j < 8; j++)
            asq[j] = sel4(*(const float4*)(g_as1 + sidx[j] * 4), q);
        uint2 pv[8];
        #pragma unroll
        for (int j = 0; j < 8; j++)
            pv[j] = *(const uint2*)(hbase + (size_t)sidx[j] * D1 + laneoff);
        #pragma unroll
        for (int j = 0; j < 8; j++) {
            float e = __expf(lrelu(asq[j] + adq));
            ssum += e;
            float2 f01 = __half22float2(*(__half2*)&pv[j].x);
            float2 f23 = __half22float2(*(__half2*)&pv[j].y);
            a0 += e * f01.x; a1 += e * f01.y; a2 += e * f23.x; a3 += e * f23.y;
        }
    }
    for (; i < end; i++) {
        int s = g_csrsrc[i];
        float e = __expf(lrelu(sel4(*(const float4*)(g_as1 + s * 4), q) + adq));
        ssum += e;
        uint2 pv = *(const uint2*)(hbase + (size_t)s * D1 + laneoff);
        float2 f01 = __half22float2(*(__half2*)&pv.x);
        float2 f23 = __half22float2(*(__half2*)&pv.y);
        a0 += e * f01.x; a1 += e * f01.y; a2 += e * f23.x; a3 += e * f23.y;
    }
    float inv = 1.f / (ssum + 1e-16f);
    const float4 bv = *(const float4*)(b1 + laneoff);
    float4 ov;
    ov.x = elu(a0 * inv + bv.x);
    ov.y = elu(a1 * inv + bv.y);
    ov.z = elu(a2 * inv + bv.z);
    ov.w = elu(a3 * inv + bv.w);
    *(float4*)(g_out1 + (size_t)n * D1 + laneoff) = ov;
}

// ---------------- GEMM2 + attention logits (thread per node) ----------------
__global__ void k_gemm2(const float* __restrict__ W2,
                        const float* __restrict__ as_w,
                        const float* __restrict__ ad_w) {
    __shared__ float sW[D1 * C2];
    __shared__ float sAs[C2], sAd[C2];
    int t = threadIdx.x;
    for (int i = t; i < D1 * C2; i += 256) sW[i] = W2[i];
    if (t < C2) { sAs[t] = as_w[t]; sAd[t] = ad_w[t]; }
    __syncthreads();
    int n = blockIdx.x * blockDim.x + t;
    if (n >= NN) return;

    float acc[C2];
    #pragma unroll
    for (int c = 0; c < C2; c++) acc[c] = 0.f;
    const float4* xp = (const float4*)(g_out1 + (size_t)n * D1);
    for (int k4 = 0; k4 < 32; k4++) {
        float4 xv = xp[k4];
        const float* w0 = sW + (k4 * 4) * C2;
        #pragma unroll
        for (int c = 0; c < C2; c++) {
            acc[c] += xv.x * w0[c] + xv.y * w0[C2 + c] + xv.z * w0[2*C2 + c] + xv.w * w0[3*C2 + c];
        }
    }
    float asum = 0.f, dsum = 0.f;
    #pragma unroll
    for (int c = 0; c < C2; c++) { asum += acc[c] * sAs[c]; dsum += acc[c] * sAd[c]; }
    g_as2[n] = asum;
    g_ad2[n] = dsum;
    float4* hp = (float4*)(g_h2 + (size_t)n * C2);
    #pragma unroll
    for (int i = 0; i < 8; i++) hp[i] = make_float4(acc[4*i], acc[4*i+1], acc[4*i+2], acc[4*i+3]);
}

// ---------------- GAT layer 2 + pooling: single-pass, warp per dst node ----------------
__global__ void k_edge2(const float* __restrict__ b2,
                        const int* __restrict__ batch) {
    int gwarp = (blockIdx.x * blockDim.x + threadIdx.x) >> 5;
    int lane = threadIdx.x & 31;
    if (gwarp >= NN) return;
    int n = gwarp;
    int beg = g_rowptr[n], end = g_rowptr[n + 1];
    float ad = g_ad2[n];

    float ssum = 0.f, acc = 0.f;
    int i = beg;
    for (; i < end && (i & 3); i++) {
        int s = g_csrsrc[i];
        float e = __expf(lrelu(g_as2[s] + ad));
        ssum += e;
        acc += e * g_h2[(size_t)s * C2 + lane];
    }
    for (; i + 8 <= end; i += 8) {
        int4 c0 = *(const int4*)(g_csrsrc + i);
        int4 c1 = *(const int4*)(g_csrsrc + i + 4);
        int sidx[8] = {c0.x, c0.y, c0.z, c0.w, c1.x, c1.y, c1.z, c1.w};
        float av[8];
        #pragma unroll
        for (int j = 0; j < 8; j++) av[j] = g_as2[sidx[j]];
        float fv[8];
        #pragma unroll
        for (int j = 0; j < 8; j++) fv[j] = g_h2[(size_t)sidx[j] * C2 + lane];
        #pragma unroll
        for (int j = 0; j < 8; j++) {
            float e = __expf(lrelu(av[j] + ad));
            ssum += e;
            acc += e * fv[j];
        }
    }
    for (; i < end; i++) {
        int s = g_csrsrc[i];
        float e = __expf(lrelu(g_as2[s] + ad));
        ssum += e;
        acc += e * g_h2[(size_t)s * C2 + lane];
    }
    float inv = 1.f / (ssum + 1e-16f);
    float v = elu(acc * inv + b2[lane]);
    int gid = batch[n];
    atomicAdd(&g_pool[gid * C2 + lane], v);
    if (lane == 0) atomicAdd(&g_cnt[gid], 1.0f);
}

// ---------------- MLP head: thread per graph ----------------
__global__ void k_head(const float* __restrict__ Wh1, const float* __restrict__ bh1,
                       const float* __restrict__ Wh2, const float* __restrict__ bh2,
                       float* __restrict__ out) {
    int g = blockIdx.x * blockDim.x + threadIdx.x;
    if (g >= GG) return;
    float cnt = fmaxf(g_cnt[g], 1.0f);
    float invc = 1.f / cnt;
    float p[C2];
    #pragma unroll
    for (int c = 0; c < C2; c++) p[c] = g_pool[g * C2 + c] * invc;
    float o = bh2[0];
    for (int j = 0; j < 64; j++) {
        float a = bh1[j];
        #pragma unroll
        for (int c = 0; c < C2; c++) a += p[c] * Wh1[c * 64 + j];
        a = fmaxf(a, 0.f);
        o += a * Wh2[j];
    }
    out[g] = o;
}

// ---------------- launch ----------------
extern "C" void kernel_launch(void* const* d_in, const int* in_sizes, int n_in,
                              void* d_out, int out_size) {
    const float* x     = (const float*)d_in[0];
    const int*   ei    = (const int*)d_in[1];
    const int*   batch = (const int*)d_in[2];
    const float* W1   = (const float*)d_in[3];
    const float* as1  = (const float*)d_in[4];
    const float* ad1  = (const float*)d_in[5];
    const float* b1   = (const float*)d_in[6];
    const float* W2   = (const float*)d_in[7];
    const float* as2  = (const float*)d_in[8];
    const float* ad2  = (const float*)d_in[9];
    const float* b2   = (const float*)d_in[10];
    const float* Wh1  = (const float*)d_in[11];
    const float* bh1  = (const float*)d_in[12];
    const float* Wh2  = (const float*)d_in[13];
    const float* bh2  = (const float*)d_in[14];
    float* out = (float*)d_out;

    k_init<<<(NN + 255) / 256, 256>>>();
    k_degree<<<(EE + 255) / 256, 256>>>(ei);
    k_scan<<<1, 1024>>>();
    k_scatter<<<(ET + 255) / 256, 256>>>(ei);
    k_gemm1<<<(NN + 63) / 64, 256>>>(x, W1, as1, ad1);
    k_edge1<<<(NN + 7) / 8, 256>>>(b1);
    k_gemm2<<<(NN + 255) / 256, 256>>>(W2, as2, ad2);
    k_edge2<<<(NN + 7) / 8, 256>>>(b2, batch);
    k_head<<<1, 128>>>(Wh1, bh1, Wh2, bh2, out);
}

// round 6
// speedup vs baseline: 1.4999x; 1.0729x over previous
#include <cuda_runtime.h>
#include <cuda_fp16.h>
#include <math.h>

#define NN 50000
#define EE 1600000
#define ET (EE + NN)     // edges + self loops
#define GG 100
#define IN_CH 16
#define H1 4
#define C1 32
#define D1 (H1*C1)       // 128
#define C2 32
#define NEG 0.2f

// ---------------- scratch ----------------
__device__ int   g_deg[NN];
__device__ int   g_rowptr[NN + 1];
__device__ int   g_cursor[NN];
__device__ __align__(16) int g_csrsrc[ET];
__device__ __align__(16) __half g_h1h[NN * D1];       // fp16 features, layer 1
__device__ __align__(16) float  g_as1[NN * H1];
__device__ __align__(16) float  g_ad1[NN * H1];
__device__ __align__(16) float  g_out1[NN * D1];
__device__ __align__(16) float  g_h2[NN * C2];
__device__ float g_as2[NN];
__device__ float g_ad2[NN];
__device__ float g_pool[GG * C2];
__device__ float g_cnt[GG];

// ---------------- init ----------------
__global__ void k_init() {
    int i = blockIdx.x * blockDim.x + threadIdx.x;
    if (i < NN) g_deg[i] = 1;           // self loop
    if (i < GG * C2) g_pool[i] = 0.f;
    if (i < GG) g_cnt[i] = 0.f;
}

// ---------------- degree count ----------------
__global__ void k_degree(const int* __restrict__ ei) {
    int e = blockIdx.x * blockDim.x + threadIdx.x;
    if (e >= EE) return;
    atomicAdd(&g_deg[ei[EE + e]], 1);
}

// ---------------- single-block exclusive scan (also fills cursor) ----------------
__global__ void k_scan() {
    __shared__ int warp_sums[32];
    __shared__ int carry_s;
    int t = threadIdx.x;
    int lane = t & 31, warp = t >> 5;
    if (t == 0) carry_s = 0;
    __syncthreads();
    for (int base = 0; base < NN; base += 1024) {
        int idx = base + t;
        int v = (idx < NN) ? g_deg[idx] : 0;
        int incl = v;
        #pragma unroll
        for (int off = 1; off < 32; off <<= 1) {
            int n = __shfl_up_sync(0xffffffffu, incl, off);
            if (lane >= off) incl += n;
        }
        if (lane == 31) warp_sums[warp] = incl;
        __syncthreads();
        if (warp == 0) {
            int ws = warp_sums[lane];
            int wincl = ws;
            #pragma unroll
            for (int off = 1; off < 32; off <<= 1) {
                int n = __shfl_up_sync(0xffffffffu, wincl, off);
                if (lane >= off) wincl += n;
            }
            warp_sums[lane] = wincl - ws;
        }
        __syncthreads();
        int carry = carry_s;
        int total_pos = carry + warp_sums[warp] + incl;
        if (idx < NN) {
            int excl = total_pos - v;
            g_rowptr[idx] = excl;
            g_cursor[idx] = excl;
        }
        __syncthreads();
        if (t == 1023) carry_s = total_pos;
        __syncthreads();
    }
    if (t == 0) g_rowptr[NN] = carry_s;
}

// ---------------- scatter edges into CSR (by dst), incl. self loops ----------------
__global__ void k_scatter(const int* __restrict__ ei) {
    int idx = blockIdx.x * blockDim.x + threadIdx.x;
    if (idx >= ET) return;
    int src, dst;
    if (idx < EE) { src = ei[idx]; dst = ei[EE + idx]; }
    else          { src = idx - EE; dst = src; }
    int slot = atomicAdd(&g_cursor[dst], 1);
    g_csrsrc[slot] = src;
}

// ---------------- GEMM1 + attention logits ----------------
__global__ void k_gemm1(const float* __restrict__ x,
                        const float* __restrict__ W1,
                        const float* __restrict__ as_w,
                        const float* __restrict__ ad_w) {
    __shared__ float sW[IN_CH * D1];
    __shared__ float sAs[H1 * C1];
    __shared__ float sAd[H1 * C1];
    int t = threadIdx.x;
    for (int i = t; i < IN_CH * D1; i += 256) sW[i] = W1[i];
    if (t < H1 * C1) { sAs[t] = as_w[t]; sAd[t] = ad_w[t]; }
    __syncthreads();

    int warp = t >> 5, lane = t & 31;
    int h = warp & 3;
    int n = blockIdx.x * 64 + (warp >> 2) * 32 + lane;
    if (n >= NN) return;

    float xv[16];
    const float4* xp = (const float4*)(x + (size_t)n * IN_CH);
    #pragma unroll
    for (int i = 0; i < 4; i++) {
        float4 r = xp[i];
        xv[4*i]=r.x; xv[4*i+1]=r.y; xv[4*i+2]=r.z; xv[4*i+3]=r.w;
    }
    float acc[C1];
    #pragma unroll
    for (int c = 0; c < C1; c++) acc[c] = 0.f;
    #pragma unroll
    for (int k = 0; k < IN_CH; k++) {
        float xk = xv[k];
        const float* wrow = sW + k * D1 + h * C1;
        #pragma unroll
        for (int c = 0; c < C1; c++) acc[c] += xk * wrow[c];
    }
    float asum = 0.f, dsum = 0.f;
    #pragma unroll
    for (int c = 0; c < C1; c++) { asum += acc[c] * sAs[h*C1+c]; dsum += acc[c] * sAd[h*C1+c]; }
    g_as1[n * H1 + h] = asum;
    g_ad1[n * H1 + h] = dsum;
    uint4 pk[4];
    unsigned* pu = (unsigned*)pk;
    #pragma unroll
    for (int i = 0; i < 16; i++) {
        __half2 hh = __floats2half2_rn(acc[2*i], acc[2*i+1]);
        pu[i] = *(unsigned*)&hh;
    }
    uint4* hp = (uint4*)(g_h1h + (size_t)n * D1 + h * C1);
    #pragma unroll
    for (int i = 0; i < 4; i++) hp[i] = pk[i];
}

__device__ __forceinline__ float lrelu(float e) { return e > 0.f ? e : NEG * e; }
__device__ __forceinline__ float elu(float v)   { return v > 0.f ? v : (__expf(v) - 1.f); }

__device__ __forceinline__ float sel4(float4 a, int q) {
    float w = a.x;
    w = (q == 1) ? a.y : w;
    w = (q == 2) ? a.z : w;
    w = (q == 3) ? a.w : w;
    return w;
}

// ---------------- GAT layer 1: tiled single-traversal, warp per dst node ----------------
// Phase A: lane-parallel exp over 32-edge tile (4 exps/lane); stash (src, alpha4) in smem.
// Phase B: warp-uniform accumulation of fp16 feature lines; lane owns ch [4l,4l+3], head l>>3.
__global__ void k_edge1(const float* __restrict__ b1) {
    __shared__ float s_alpha[8][32][4];
    __shared__ int   s_src[8][32];
    int w = threadIdx.x >> 5;
    int lane = threadIdx.x & 31;
    int n = blockIdx.x * 8 + w;
    if (n >= NN) return;
    int beg = g_rowptr[n], end = g_rowptr[n + 1];
    float4 ad = *(const float4*)(g_ad1 + n * 4);
    int q = lane >> 3;
    int laneoff = lane * 4;
    const __half* hbase = g_h1h;

    float s0 = 0.f, s1 = 0.f, s2 = 0.f, s3 = 0.f;   // per-lane partial head sums
    float a0 = 0.f, a1 = 0.f, a2 = 0.f, a3 = 0.f;   // feature accumulators

    for (int base = beg; base < end; base += 32) {
        int i = base + lane;
        int cnt = min(32, end - base);
        // Phase A
        if (i < end) {
            int s = g_csrsrc[i];
            float4 as = *(const float4*)(g_as1 + s * 4);
            float e0 = __expf(lrelu(as.x + ad.x));
            float e1 = __expf(lrelu(as.y + ad.y));
            float e2 = __expf(lrelu(as.z + ad.z));
            float e3 = __expf(lrelu(as.w + ad.w));
            s0 += e0; s1 += e1; s2 += e2; s3 += e3;
            s_src[w][lane] = s;
            s_alpha[w][lane][0] = e0;
            s_alpha[w][lane][1] = e1;
            s_alpha[w][lane][2] = e2;
            s_alpha[w][lane][3] = e3;
        }
        __syncwarp();
        // Phase B: uniform walk
        int j = 0;
        for (; j + 4 <= cnt; j += 4) {
            int  sj0 = s_src[w][j],     sj1 = s_src[w][j + 1];
            int  sj2 = s_src[w][j + 2], sj3 = s_src[w][j + 3];
            float w0 = s_alpha[w][j][q],     w1 = s_alpha[w][j + 1][q];
            float w2 = s_alpha[w][j + 2][q], w3 = s_alpha[w][j + 3][q];
            uint2 p0 = *(const uint2*)(hbase + (size_t)sj0 * D1 + laneoff);
            uint2 p1 = *(const uint2*)(hbase + (size_t)sj1 * D1 + laneoff);
            uint2 p2 = *(const uint2*)(hbase + (size_t)sj2 * D1 + laneoff);
            uint2 p3 = *(const uint2*)(hbase + (size_t)sj3 * D1 + laneoff);
            float2 f;
            f = __half22float2(*(__half2*)&p0.x); a0 += w0 * f.x; a1 += w0 * f.y;
            f = __half22float2(*(__half2*)&p0.y); a2 += w0 * f.x; a3 += w0 * f.y;
            f = __half22float2(*(__half2*)&p1.x); a0 += w1 * f.x; a1 += w1 * f.y;
            f = __half22float2(*(__half2*)&p1.y); a2 += w1 * f.x; a3 += w1 * f.y;
            f = __half22float2(*(__half2*)&p2.x); a0 += w2 * f.x; a1 += w2 * f.y;
            f = __half22float2(*(__half2*)&p2.y); a2 += w2 * f.x; a3 += w2 * f.y;
            f = __half22float2(*(__half2*)&p3.x); a0 += w3 * f.x; a1 += w3 * f.y;
            f = __half22float2(*(__half2*)&p3.y); a2 += w3 * f.x; a3 += w3 * f.y;
        }
        for (; j < cnt; j++) {
            int  sj = s_src[w][j];
            float ww = s_alpha[w][j][q];
            uint2 pv = *(const uint2*)(hbase + (size_t)sj * D1 + laneoff);
            float2 f01 = __half22float2(*(__half2*)&pv.x);
            float2 f23 = __half22float2(*(__half2*)&pv.y);
            a0 += ww * f01.x; a1 += ww * f01.y; a2 += ww * f23.x; a3 += ww * f23.y;
        }
        __syncwarp();
    }
    // reduce head sums across warp
    #pragma unroll
    for (int off = 16; off; off >>= 1) {
        s0 += __shfl_xor_sync(0xffffffffu, s0, off);
        s1 += __shfl_xor_sync(0xffffffffu, s1, off);
        s2 += __shfl_xor_sync(0xffffffffu, s2, off);
        s3 += __shfl_xor_sync(0xffffffffu, s3, off);
    }
    float inv = sel4(make_float4(1.f/(s0+1e-16f), 1.f/(s1+1e-16f),
                                 1.f/(s2+1e-16f), 1.f/(s3+1e-16f)), q);
    const float4 bv = *(const float4*)(b1 + laneoff);
    float4 ov;
    ov.x = elu(a0 * inv + bv.x);
    ov.y = elu(a1 * inv + bv.y);
    ov.z = elu(a2 * inv + bv.z);
    ov.w = elu(a3 * inv + bv.w);
    *(float4*)(g_out1 + (size_t)n * D1 + laneoff) = ov;
}

// ---------------- GEMM2 + attention logits (thread per node) ----------------
__global__ void k_gemm2(const float* __restrict__ W2,
                        const float* __restrict__ as_w,
                        const float* __restrict__ ad_w) {
    __shared__ float sW[D1 * C2];
    __shared__ float sAs[C2], sAd[C2];
    int t = threadIdx.x;
    for (int i = t; i < D1 * C2; i += 256) sW[i] = W2[i];
    if (t < C2) { sAs[t] = as_w[t]; sAd[t] = ad_w[t]; }
    __syncthreads();
    int n = blockIdx.x * blockDim.x + t;
    if (n >= NN) return;

    float acc[C2];
    #pragma unroll
    for (int c = 0; c < C2; c++) acc[c] = 0.f;
    const float4* xp = (const float4*)(g_out1 + (size_t)n * D1);
    for (int k4 = 0; k4 < 32; k4++) {
        float4 xv = xp[k4];
        const float* w0 = sW + (k4 * 4) * C2;
        #pragma unroll
        for (int c = 0; c < C2; c++) {
            acc[c] += xv.x * w0[c] + xv.y * w0[C2 + c] + xv.z * w0[2*C2 + c] + xv.w * w0[3*C2 + c];
        }
    }
    float asum = 0.f, dsum = 0.f;
    #pragma unroll
    for (int c = 0; c < C2; c++) { asum += acc[c] * sAs[c]; dsum += acc[c] * sAd[c]; }
    g_as2[n] = asum;
    g_ad2[n] = dsum;
    float4* hp = (float4*)(g_h2 + (size_t)n * C2);
    #pragma unroll
    for (int i = 0; i < 8; i++) hp[i] = make_float4(acc[4*i], acc[4*i+1], acc[4*i+2], acc[4*i+3]);
}

// ---------------- GAT layer 2 + pooling: tiled single-traversal ----------------
__global__ void k_edge2(const float* __restrict__ b2,
                        const int* __restrict__ batch) {
    __shared__ float s_alpha[8][32];
    __shared__ int   s_src[8][32];
    int w = threadIdx.x >> 5;
    int lane = threadIdx.x & 31;
    int n = blockIdx.x * 8 + w;
    if (n >= NN) return;
    int beg = g_rowptr[n], end = g_rowptr[n + 1];
    float ad = g_ad2[n];

    float ssum = 0.f, acc = 0.f;
    for (int base = beg; base < end; base += 32) {
        int i = base + lane;
        int cnt = min(32, end - base);
        if (i < end) {
            int s = g_csrsrc[i];
            float e = __expf(lrelu(g_as2[s] + ad));
            ssum += e;
            s_src[w][lane] = s;
            s_alpha[w][lane] = e;
        }
        __syncwarp();
        int j = 0;
        for (; j + 4 <= cnt; j += 4) {
            int  sj0 = s_src[w][j],     sj1 = s_src[w][j + 1];
            int  sj2 = s_src[w][j + 2], sj3 = s_src[w][j + 3];
            float w0 = s_alpha[w][j],     w1 = s_alpha[w][j + 1];
            float w2 = s_alpha[w][j + 2], w3 = s_alpha[w][j + 3];
            float f0 = g_h2[(size_t)sj0 * C2 + lane];
            float f1 = g_h2[(size_t)sj1 * C2 + lane];
            float f2 = g_h2[(size_t)sj2 * C2 + lane];
            float f3 = g_h2[(size_t)sj3 * C2 + lane];
            acc += w0 * f0 + w1 * f1 + w2 * f2 + w3 * f3;
        }
        for (; j < cnt; j++) {
            acc += s_alpha[w][j] * g_h2[(size_t)s_src[w][j] * C2 + lane];
        }
        __syncwarp();
    }
    #pragma unroll
    for (int off = 16; off; off >>= 1) ssum += __shfl_xor_sync(0xffffffffu, ssum, off);
    float inv = 1.f / (ssum + 1e-16f);
    float v = elu(acc * inv + b2[lane]);
    int gid = batch[n];
    atomicAdd(&g_pool[gid * C2 + lane], v);
    if (lane == 0) atomicAdd(&g_cnt[gid], 1.0f);
}

// ---------------- MLP head: thread per graph ----------------
__global__ void k_head(const float* __restrict__ Wh1, const float* __restrict__ bh1,
                       const float* __restrict__ Wh2, const float* __restrict__ bh2,
                       float* __restrict__ out) {
    int g = blockIdx.x * blockDim.x + threadIdx.x;
    if (g >= GG) return;
    float cnt = fmaxf(g_cnt[g], 1.0f);
    float invc = 1.f / cnt;
    float p[C2];
    #pragma unroll
    for (int c = 0; c < C2; c++) p[c] = g_pool[g * C2 + c] * invc;
    float o = bh2[0];
    for (int j = 0; j < 64; j++) {
        float a = bh1[j];
        #pragma unroll
        for (int c = 0; c < C2; c++) a += p[c] * Wh1[c * 64 + j];
        a = fmaxf(a, 0.f);
        o += a * Wh2[j];
    }
    out[g] = o;
}

// ---------------- launch ----------------
extern "C" void kernel_launch(void* const* d_in, const int* in_sizes, int n_in,
                              void* d_out, int out_size) {
    const float* x     = (const float*)d_in[0];
    const int*   ei    = (const int*)d_in[1];
    const int*   batch = (const int*)d_in[2];
    const float* W1   = (const float*)d_in[3];
    const float* as1  = (const float*)d_in[4];
    const float* ad1  = (const float*)d_in[5];
    const float* b1   = (const float*)d_in[6];
    const float* W2   = (const float*)d_in[7];
    const float* as2  = (const float*)d_in[8];
    const float* ad2  = (const float*)d_in[9];
    const float* b2   = (const float*)d_in[10];
    const float* Wh1  = (const float*)d_in[11];
    const float* bh1  = (const float*)d_in[12];
    const float* Wh2  = (const float*)d_in[13];
    const float* bh2  = (const float*)d_in[14];
    float* out = (float*)d_out;

    k_init<<<(NN + 255) / 256, 256>>>();
    k_degree<<<(EE + 255) / 256, 256>>>(ei);
    k_scan<<<1, 1024>>>();
    k_scatter<<<(ET + 255) / 256, 256>>>(ei);
    k_gemm1<<<(NN + 63) / 64, 256>>>(x, W1, as1, ad1);
    k_edge1<<<(NN + 7) / 8, 256>>>(b1);
    k_gemm2<<<(NN + 255) / 256, 256>>>(W2, as2, ad2);
    k_edge2<<<(NN + 7) / 8, 256>>>(b2, batch);
    k_head<<<1, 128>>>(Wh1, bh1, Wh2, bh2, out);
}

// round 7
// speedup vs baseline: 1.5661x; 1.0442x over previous
#include <cuda_runtime.h>
#include <cuda_fp16.h>
#include <math.h>

#define NN 50000
#define EE 1600000
#define ET (EE + NN)     // edges + self loops
#define GG 100
#define IN_CH 16
#define H1 4
#define C1 32
#define D1 (H1*C1)       // 128
#define C2 32
#define NEG 0.2f

#define DEG_BLOCKS ((EE + 255) / 256)
#define SCAT_BLOCKS ((ET + 255) / 256)
#define GEMM1_BLOCKS ((NN + 63) / 64)

// ---------------- scratch ----------------
__device__ __align__(16) int g_deg[NN + 4];     // zeroed at module load; re-zeroed by scan
__device__ __align__(16) int g_rowptr[NN + 4];
__device__ __align__(16) int g_cursor[NN + 4];
__device__ __align__(16) int g_csrsrc[ET];
__device__ __align__(16) __half g_h1h[NN * D1];
__device__ __align__(16) float  g_as1[NN * H1];
__device__ __align__(16) float  g_ad1[NN * H1];
__device__ __align__(16) float  g_out1[NN * D1];
__device__ __align__(16) float  g_h2[NN * C2];
__device__ float g_as2[NN];
__device__ float g_ad2[NN];
__device__ float g_pool[GG * C2];
__device__ float g_cnt[GG];

// ---------------- fat kernel: degree count + pool init ----------------
__global__ void k_degree(const int* __restrict__ ei) {
    int b = blockIdx.x;
    if (b < DEG_BLOCKS) {
        int e = b * 256 + threadIdx.x;
        if (e < EE) atomicAdd(&g_deg[ei[EE + e]], 1);
    } else {
        // one extra block: zero pool + cnt
        int i = threadIdx.x;
        for (; i < GG * C2; i += 256) g_pool[i] = 0.f;
        int j = threadIdx.x;
        if (j < GG) g_cnt[j] = 0.f;
    }
}

// ---------------- single-block exclusive scan, 4 elems/thread ----------------
// rowptr[i] = prefix of (deg[i] + 1)  (self loop baked in); also zeroes g_deg.
__global__ void k_scan() {
    __shared__ int warp_sums[32];
    __shared__ int carry_s;
    int t = threadIdx.x;
    int lane = t & 31, warp = t >> 5;
    if (t == 0) carry_s = 0;
    __syncthreads();
    const int CHUNK = 4096;   // 1024 threads * 4
    for (int base = 0; base < NN; base += CHUNK) {
        int idx = base + t * 4;
        int4 v4 = make_int4(0, 0, 0, 0);
        if (idx < NN) {
            v4 = *(const int4*)(g_deg + idx);
            *(int4*)(g_deg + idx) = make_int4(0, 0, 0, 0);   // reset for next call
            v4.x += 1; v4.y += 1; v4.z += 1; v4.w += 1;      // self loops
        }
        int v = v4.x + v4.y + v4.z + v4.w;
        int incl = v;
        #pragma unroll
        for (int off = 1; off < 32; off <<= 1) {
            int nb = __shfl_up_sync(0xffffffffu, incl, off);
            if (lane >= off) incl += nb;
        }
        if (lane == 31) warp_sums[warp] = incl;
        __syncthreads();
        if (warp == 0) {
            int ws = warp_sums[lane];
            int wincl = ws;
            #pragma unroll
            for (int off = 1; off < 32; off <<= 1) {
                int nb = __shfl_up_sync(0xffffffffu, wincl, off);
                if (lane >= off) wincl += nb;
            }
            warp_sums[lane] = wincl - ws;
        }
        __syncthreads();
        int carry = carry_s;
        int excl = carry + warp_sums[warp] + incl - v;   // exclusive prefix of first of 4
        if (idx < NN) {
            int4 r;
            r.x = excl;
            r.y = r.x + v4.x;
            r.z = r.y + v4.y;
            r.w = r.z + v4.z;
            *(int4*)(g_rowptr + idx) = r;
            *(int4*)(g_cursor + idx) = r;
        }
        __syncthreads();
        if (t == 1023) carry_s = carry + warp_sums[31] + incl;
        __syncthreads();
    }
    if (t == 0) g_rowptr[NN] = carry_s;
}

// ---------------- GEMM1 device body ----------------
__device__ __forceinline__ void gemm1_body(int blk,
                        const float* __restrict__ x,
                        const float* __restrict__ W1,
                        const float* __restrict__ as_w,
                        const float* __restrict__ ad_w,
                        float* sW, float* sAs, float* sAd) {
    int t = threadIdx.x;
    for (int i = t; i < IN_CH * D1; i += 256) sW[i] = W1[i];
    if (t < H1 * C1) { sAs[t] = as_w[t]; sAd[t] = ad_w[t]; }
    __syncthreads();

    int warp = t >> 5, lane = t & 31;
    int h = warp & 3;
    int n = blk * 64 + (warp >> 2) * 32 + lane;
    if (n >= NN) return;

    float xv[16];
    const float4* xp = (const float4*)(x + (size_t)n * IN_CH);
    #pragma unroll
    for (int i = 0; i < 4; i++) {
        float4 r = xp[i];
        xv[4*i]=r.x; xv[4*i+1]=r.y; xv[4*i+2]=r.z; xv[4*i+3]=r.w;
    }
    float acc[C1];
    #pragma unroll
    for (int c = 0; c < C1; c++) acc[c] = 0.f;
    #pragma unroll
    for (int k = 0; k < IN_CH; k++) {
        float xk = xv[k];
        const float* wrow = sW + k * D1 + h * C1;
        #pragma unroll
        for (int c = 0; c < C1; c++) acc[c] += xk * wrow[c];
    }
    float asum = 0.f, dsum = 0.f;
    #pragma unroll
    for (int c = 0; c < C1; c++) { asum += acc[c] * sAs[h*C1+c]; dsum += acc[c] * sAd[h*C1+c]; }
    g_as1[n * H1 + h] = asum;
    g_ad1[n * H1 + h] = dsum;
    uint4 pk[4];
    unsigned* pu = (unsigned*)pk;
    #pragma unroll
    for (int i = 0; i < 16; i++) {
        __half2 hh = __floats2half2_rn(acc[2*i], acc[2*i+1]);
        pu[i] = *(unsigned*)&hh;
    }
    uint4* hp = (uint4*)(g_h1h + (size_t)n * D1 + h * C1);
    #pragma unroll
    for (int i = 0; i < 4; i++) hp[i] = pk[i];
}

// ---------------- fat kernel: scatter (CSR build) + gemm1 ----------------
__global__ void __launch_bounds__(256) k_scatter_gemm1(
        const int* __restrict__ ei,
        const float* __restrict__ x,
        const float* __restrict__ W1,
        const float* __restrict__ as_w,
        const float* __restrict__ ad_w) {
    __shared__ float sW[IN_CH * D1 + 2 * H1 * C1];
    int b = blockIdx.x;
    if (b < SCAT_BLOCKS) {
        int idx = b * 256 + threadIdx.x;
        if (idx >= ET) return;
        int src, dst;
        if (idx < EE) { src = ei[idx]; dst = ei[EE + idx]; }
        else          { src = idx - EE; dst = src; }
        int slot = atomicAdd(&g_cursor[dst], 1);
        g_csrsrc[slot] = src;
    } else {
        gemm1_body(b - SCAT_BLOCKS, x, W1, as_w, ad_w,
                   sW, sW + IN_CH * D1, sW + IN_CH * D1 + H1 * C1);
    }
}

__device__ __forceinline__ float lrelu(float e) { return e > 0.f ? e : NEG * e; }
__device__ __forceinline__ float elu(float v)   { return v > 0.f ? v : (__expf(v) - 1.f); }

__device__ __forceinline__ float sel4(float4 a, int q) {
    float w = a.x;
    w = (q == 1) ? a.y : w;
    w = (q == 2) ? a.z : w;
    w = (q == 3) ? a.w : w;
    return w;
}

// ---------------- GAT layer 1: tiled single-traversal, warp per dst node ----------------
__global__ void __launch_bounds__(256) k_edge1(const float* __restrict__ b1) {
    __shared__ float s_alpha[8][32][4];
    __shared__ int   s_src[8][32];
    int w = threadIdx.x >> 5;
    int lane = threadIdx.x & 31;
    int n = blockIdx.x * 8 + w;
    if (n >= NN) return;
    int beg = g_rowptr[n], end = g_rowptr[n + 1];
    float4 ad = *(const float4*)(g_ad1 + n * 4);
    int q = lane >> 3;
    int laneoff = lane * 4;
    const __half* hbase = g_h1h;

    float s0 = 0.f, s1 = 0.f, s2 = 0.f, s3 = 0.f;
    float a0 = 0.f, a1 = 0.f, a2 = 0.f, a3 = 0.f;

    for (int base = beg; base < end; base += 32) {
        int i = base + lane;
        int cnt = min(32, end - base);
        // Phase A: lane-parallel exp
        if (i < end) {
            int s = g_csrsrc[i];
            float4 as = *(const float4*)(g_as1 + s * 4);
            float e0 = __expf(lrelu(as.x + ad.x));
            float e1 = __expf(lrelu(as.y + ad.y));
            float e2 = __expf(lrelu(as.z + ad.z));
            float e3 = __expf(lrelu(as.w + ad.w));
            s0 += e0; s1 += e1; s2 += e2; s3 += e3;
            s_src[w][lane] = s;
            s_alpha[w][lane][0] = e0;
            s_alpha[w][lane][1] = e1;
            s_alpha[w][lane][2] = e2;
            s_alpha[w][lane][3] = e3;
        }
        __syncwarp();
        // Phase B: warp-uniform, 8-deep load pipeline
        int j = 0;
        for (; j + 8 <= cnt; j += 8) {
            int   sj[8];
            float wj[8];
            uint2 pj[8];
            #pragma unroll
            for (int k = 0; k < 8; k++) { sj[k] = s_src[w][j + k]; wj[k] = s_alpha[w][j + k][q]; }
            #pragma unroll
            for (int k = 0; k < 8; k++) pj[k] = *(const uint2*)(hbase + (size_t)sj[k] * D1 + laneoff);
            #pragma unroll
            for (int k = 0; k < 8; k++) {
                float2 f01 = __half22float2(*(__half2*)&pj[k].x);
                float2 f23 = __half22float2(*(__half2*)&pj[k].y);
                a0 += wj[k] * f01.x; a1 += wj[k] * f01.y;
                a2 += wj[k] * f23.x; a3 += wj[k] * f23.y;
            }
        }
        for (; j < cnt; j++) {
            int  sj = s_src[w][j];
            float ww = s_alpha[w][j][q];
            uint2 pv = *(const uint2*)(hbase + (size_t)sj * D1 + laneoff);
            float2 f01 = __half22float2(*(__half2*)&pv.x);
            float2 f23 = __half22float2(*(__half2*)&pv.y);
            a0 += ww * f01.x; a1 += ww * f01.y; a2 += ww * f23.x; a3 += ww * f23.y;
        }
        __syncwarp();
    }
    #pragma unroll
    for (int off = 16; off; off >>= 1) {
        s0 += __shfl_xor_sync(0xffffffffu, s0, off);
        s1 += __shfl_xor_sync(0xffffffffu, s1, off);
        s2 += __shfl_xor_sync(0xffffffffu, s2, off);
        s3 += __shfl_xor_sync(0xffffffffu, s3, off);
    }
    float inv = sel4(make_float4(1.f/(s0+1e-16f), 1.f/(s1+1e-16f),
                                 1.f/(s2+1e-16f), 1.f/(s3+1e-16f)), q);
    const float4 bv = *(const float4*)(b1 + laneoff);
    float4 ov;
    ov.x = elu(a0 * inv + bv.x);
    ov.y = elu(a1 * inv + bv.y);
    ov.z = elu(a2 * inv + bv.z);
    ov.w = elu(a3 * inv + bv.w);
    *(float4*)(g_out1 + (size_t)n * D1 + laneoff) = ov;
}

// ---------------- GEMM2 + attention logits (thread per node) ----------------
__global__ void k_gemm2(const float* __restrict__ W2,
                        const float* __restrict__ as_w,
                        const float* __restrict__ ad_w) {
    __shared__ float sW[D1 * C2];
    __shared__ float sAs[C2], sAd[C2];
    int t = threadIdx.x;
    for (int i = t; i < D1 * C2; i += 256) sW[i] = W2[i];
    if (t < C2) { sAs[t] = as_w[t]; sAd[t] = ad_w[t]; }
    __syncthreads();
    int n = blockIdx.x * blockDim.x + t;
    if (n >= NN) return;

    float acc[C2];
    #pragma unroll
    for (int c = 0; c < C2; c++) acc[c] = 0.f;
    const float4* xp = (const float4*)(g_out1 + (size_t)n * D1);
    for (int k4 = 0; k4 < 32; k4++) {
        float4 xv = xp[k4];
        const float* w0 = sW + (k4 * 4) * C2;
        #pragma unroll
        for (int c = 0; c < C2; c++) {
            acc[c] += xv.x * w0[c] + xv.y * w0[C2 + c] + xv.z * w0[2*C2 + c] + xv.w * w0[3*C2 + c];
        }
    }
    float asum = 0.f, dsum = 0.f;
    #pragma unroll
    for (int c = 0; c < C2; c++) { asum += acc[c] * sAs[c]; dsum += acc[c] * sAd[c]; }
    g_as2[n] = asum;
    g_ad2[n] = dsum;
    float4* hp = (float4*)(g_h2 + (size_t)n * C2);
    #pragma unroll
    for (int i = 0; i < 8; i++) hp[i] = make_float4(acc[4*i], acc[4*i+1], acc[4*i+2], acc[4*i+3]);
}

// ---------------- GAT layer 2 + pooling: tiled single-traversal ----------------
__global__ void __launch_bounds__(256) k_edge2(const float* __restrict__ b2,
                        const int* __restrict__ batch) {
    __shared__ float s_alpha[8][32];
    __shared__ int   s_src[8][32];
    int w = threadIdx.x >> 5;
    int lane = threadIdx.x & 31;
    int n = blockIdx.x * 8 + w;
    if (n >= NN) return;
    int beg = g_rowptr[n], end = g_rowptr[n + 1];
    float ad = g_ad2[n];

    float ssum = 0.f, acc = 0.f;
    for (int base = beg; base < end; base += 32) {
        int i = base + lane;
        int cnt = min(32, end - base);
        if (i < end) {
            int s = g_csrsrc[i];
            float e = __expf(lrelu(g_as2[s] + ad));
            ssum += e;
            s_src[w][lane] = s;
            s_alpha[w][lane] = e;
        }
        __syncwarp();
        int j = 0;
        for (; j + 8 <= cnt; j += 8) {
            int   sj[8];
            float wj[8];
            float fj[8];
            #pragma unroll
            for (int k = 0; k < 8; k++) { sj[k] = s_src[w][j + k]; wj[k] = s_alpha[w][j + k]; }
            #pragma unroll
            for (int k = 0; k < 8; k++) fj[k] = g_h2[(size_t)sj[k] * C2 + lane];
            #pragma unroll
            for (int k = 0; k < 8; k++) acc += wj[k] * fj[k];
        }
        for (; j < cnt; j++) {
            acc += s_alpha[w][j] * g_h2[(size_t)s_src[w][j] * C2 + lane];
        }
        __syncwarp();
    }
    #pragma unroll
    for (int off = 16; off; off >>= 1) ssum += __shfl_xor_sync(0xffffffffu, ssum, off);
    float inv = 1.f / (ssum + 1e-16f);
    float v = elu(acc * inv + b2[lane]);
    int gid = batch[n];
    atomicAdd(&g_pool[gid * C2 + lane], v);
    if (lane == 0) atomicAdd(&g_cnt[gid], 1.0f);
}

// ---------------- MLP head: thread per graph ----------------
__global__ void k_head(const float* __restrict__ Wh1, const float* __restrict__ bh1,
                       const float* __restrict__ Wh2, const float* __restrict__ bh2,
                       float* __restrict__ out) {
    int g = blockIdx.x * blockDim.x + threadIdx.x;
    if (g >= GG) return;
    float cnt = fmaxf(g_cnt[g], 1.0f);
    float invc = 1.f / cnt;
    float p[C2];
    #pragma unroll
    for (int c = 0; c < C2; c++) p[c] = g_pool[g * C2 + c] * invc;
    float o = bh2[0];
    for (int j = 0; j < 64; j++) {
        float a = bh1[j];
        #pragma unroll
        for (int c = 0; c < C2; c++) a += p[c] * Wh1[c * 64 + j];
        a = fmaxf(a, 0.f);
        o += a * Wh2[j];
    }
    out[g] = o;
}

// ---------------- launch ----------------
extern "C" void kernel_launch(void* const* d_in, const int* in_sizes, int n_in,
                              void* d_out, int out_size) {
    const float* x     = (const float*)d_in[0];
    const int*   ei    = (const int*)d_in[1];
    const int*   batch = (const int*)d_in[2];
    const float* W1   = (const float*)d_in[3];
    const float* as1  = (const float*)d_in[4];
    const float* ad1  = (const float*)d_in[5];
    const float* b1   = (const float*)d_in[6];
    const float* W2   = (const float*)d_in[7];
    const float* as2  = (const float*)d_in[8];
    const float* ad2  = (const float*)d_in[9];
    const float* b2   = (const float*)d_in[10];
    const float* Wh1  = (const float*)d_in[11];
    const float* bh1  = (const float*)d_in[12];
    const float* Wh2  = (const float*)d_in[13];
    const float* bh2  = (const float*)d_in[14];
    float* out = (float*)d_out;

    k_degree<<<DEG_BLOCKS + 1, 256>>>(ei);                 // degree + pool init
    k_scan<<<1, 1024>>>();                                  // rowptr/cursor (+1 self loop), zero deg
    k_scatter_gemm1<<<SCAT_BLOCKS + GEMM1_BLOCKS, 256>>>(ei, x, W1, as1, ad1);
    k_edge1<<<(NN + 7) / 8, 256>>>(b1);
    k_gemm2<<<(NN + 255) / 256, 256>>>(W2, as2, ad2);
    k_edge2<<<(NN + 7) / 8, 256>>>(b2, batch);
    k_head<<<1, 128>>>(Wh1, bh1, Wh2, bh2, out);
}